// round 1
// baseline (speedup 1.0000x reference)
#include <cuda_runtime.h>
#include <math.h>
#include <stdint.h>

// Problem dims
#define NB 8
#define ND 64
#define NT 12
#define NN 512
#define NBT (NB*NT)            // 96
#define ATT_SCALE 0.35355339059327373f   // 8^-0.5

// Scratch (static __device__ — no allocations allowed)
__device__ float d_wc[6*64*32];            // combined weights [g][i(64)][o(32)]
__device__ float d_bc[6*32];               // combined biases  [g][o]
__device__ float d_qkv[6*NBT*32*NN];       // [g][bt][o][n]
__device__ float d_attn[2*NB*4*NT*NN*8];   // [blk][b][(h*T+t)*N*8 + n*8 + d]
__device__ unsigned char d_mask[NN*NN];
__device__ int d_mask_mode;

struct WPtrs { const float* w[6]; const float* b[6]; };

// ---------------------------------------------------------------------------
// Kernel 0: fold proj1 into the 6 QKV projections.
// Wc[g] = WX[g] @ Wproj1  (32x64), bc[g] = WX[g] @ bproj1 + bX[g]
// Stored transposed as [i][o] for broadcast-friendly smem reads later.
// ---------------------------------------------------------------------------
__global__ void k_combine(const float* __restrict__ wp, const float* __restrict__ bp, WPtrs P) {
    int tid = threadIdx.x;
    for (int idx = tid; idx < 6*64*32; idx += 256) {
        int g = idx / 2048;
        int r = idx & 2047;
        int i = r >> 5;      // 0..63 (input channel of x)
        int o = r & 31;      // 0..31 (output channel)
        const float* wx = P.w[g];
        float acc = 0.f;
        #pragma unroll
        for (int c = 0; c < 32; c++) acc += wx[o*32 + c] * wp[c*64 + i];
        d_wc[idx] = acc;     // layout [g][i][o]
    }
    for (int idx = tid; idx < 6*32; idx += 256) {
        int g = idx >> 5, o = idx & 31;
        const float* wx = P.w[g];
        float acc = P.b[g][o];
        for (int c = 0; c < 32; c++) acc += wx[o*32 + c] * bp[c];
        d_bc[idx] = acc;
    }
}

// ---------------------------------------------------------------------------
// Mask dtype detection + canonicalization.
// int32 0/1 array: every 4-byte word is 0 or 1.
// float32 0/1 array: every word is 0.0f or 1.0f bits.
// uint8 0/1 array read as words: values like 0x01000101 — neither.
// ---------------------------------------------------------------------------
__global__ void k_maskdetect(const void* __restrict__ m) {
    __shared__ int oki, okf;
    if (threadIdx.x == 0) { oki = 1; okf = 1; }
    __syncthreads();
    const unsigned int* p = (const unsigned int*)m;
    for (int idx = threadIdx.x; idx < 4096; idx += 256) {
        unsigned int v = p[idx];
        if (v != 0u && v != 1u) oki = 0;            // benign race, all write 0
        float f = __uint_as_float(v);
        if (f != 0.0f && f != 1.0f) okf = 0;
    }
    __syncthreads();
    if (threadIdx.x == 0) d_mask_mode = oki ? 0 : (okf ? 1 : 2);
}

__global__ void k_maskconv(const void* __restrict__ m) {
    int idx = blockIdx.x * 256 + threadIdx.x;
    int mode = d_mask_mode;
    bool mm;
    if (mode == 0)      mm = ((const int*)m)[idx] != 0;
    else if (mode == 1) mm = ((const float*)m)[idx] != 0.0f;
    else                mm = ((const unsigned char*)m)[idx] != 0;
    d_mask[idx] = mm ? 1 : 0;
}

// ---------------------------------------------------------------------------
// Kernel 1: QKV for both attention blocks straight from x.
// Per block: (bt, n-tile of 128). Register-tiled 4x4 per thread.
// ---------------------------------------------------------------------------
__global__ __launch_bounds__(256) void k_qkv(const float* __restrict__ x) {
    __shared__ float xs[64*128];   // [ci][n]
    __shared__ float ws[64*32];    // [ci][o]
    int bt = blockIdx.x;
    int ntile = blockIdx.y;
    int b = bt / NT, t = bt % NT;
    int tid = threadIdx.x;

    for (int idx = tid; idx < 64*128; idx += 256) {
        int ci = idx >> 7, n = idx & 127;
        xs[idx] = x[((b*64 + ci)*NT + t)*NN + ntile*128 + n];
    }

    int nt = tid & 31, grp = tid >> 5;     // warp id = grp -> same o across warp
    int n0 = nt*4, o0 = grp*4;

    for (int g = 0; g < 6; g++) {
        __syncthreads();
        for (int idx = tid; idx < 2048; idx += 256) ws[idx] = d_wc[g*2048 + idx];
        __syncthreads();

        float acc[4][4];
        #pragma unroll
        for (int i = 0; i < 4; i++) {
            float bias = d_bc[g*32 + o0 + i];
            #pragma unroll
            for (int j = 0; j < 4; j++) acc[i][j] = bias;
        }
        #pragma unroll 4
        for (int ci = 0; ci < 64; ci++) {
            float4 xv = *(const float4*)&xs[ci*128 + n0];
            float4 wv = *(const float4*)&ws[ci*32 + o0];   // broadcast within warp
            float xa[4] = {xv.x, xv.y, xv.z, xv.w};
            float wa[4] = {wv.x, wv.y, wv.z, wv.w};
            #pragma unroll
            for (int i = 0; i < 4; i++)
                #pragma unroll
                for (int j = 0; j < 4; j++) acc[i][j] += wa[i]*xa[j];
        }
        #pragma unroll
        for (int i = 0; i < 4; i++) {
            float4 v = make_float4(acc[i][0], acc[i][1], acc[i][2], acc[i][3]);
            *(float4*)&d_qkv[((g*NBT + bt)*32 + o0 + i)*NN + ntile*128 + n0] = v;
        }
    }
}

// ---------------------------------------------------------------------------
// Kernel 2: attention. One CTA per (bt, head, block). 8 warps.
// Each warp processes 4 query rows at a time (K/V smem loads amortized 4x).
// ---------------------------------------------------------------------------
__global__ __launch_bounds__(256) void k_attn() {
    __shared__ float qs[8*NN], ks[8*NN], vs[8*NN];   // 48KB total
    int bt = blockIdx.x, h = blockIdx.y, blk = blockIdx.z;
    int gbase = blk * 3;             // blk 0 -> groups 0..2 (geo, masked); blk 1 -> 3..5 (plain)
    bool masked = (blk == 0);
    int tid = threadIdx.x, lane = tid & 31, w = tid >> 5;

    for (int idx = tid; idx < 8*NN; idx += 256) {
        int dd = idx >> 9, n = idx & 511;
        int c = h*8 + dd;
        qs[idx] = d_qkv[(( gbase   *NBT + bt)*32 + c)*NN + n] * ATT_SCALE;
        ks[idx] = d_qkv[(((gbase+1)*NBT + bt)*32 + c)*NN + n];
        vs[idx] = d_qkv[(((gbase+2)*NBT + bt)*32 + c)*NN + n];
    }
    __syncthreads();

    int b = bt / NT, t = bt % NT;
    float* outp = d_attn + (blk*NB + b)*(4*NT*NN*8) + (h*NT + t)*(NN*8);

    for (int grpi = w; grpi < 128; grpi += 8) {
        int n0 = grpi * 4;
        float q[4][8];
        #pragma unroll
        for (int r = 0; r < 4; r++)
            #pragma unroll
            for (int dd = 0; dd < 8; dd++) q[r][dd] = qs[dd*NN + n0 + r];

        float s[4][16];
        #pragma unroll
        for (int i = 0; i < 16; i++) {
            int j = lane + 32*i;
            float kd[8];
            #pragma unroll
            for (int dd = 0; dd < 8; dd++) kd[dd] = ks[dd*NN + j];
            #pragma unroll
            for (int r = 0; r < 4; r++) {
                float acc = 0.f;
                #pragma unroll
                for (int dd = 0; dd < 8; dd++) acc += q[r][dd]*kd[dd];
                s[r][i] = acc;
            }
        }
        if (masked) {
            #pragma unroll
            for (int i = 0; i < 16; i++) {
                int j = lane + 32*i;
                #pragma unroll
                for (int r = 0; r < 4; r++)
                    if (d_mask[(n0 + r)*NN + j]) s[r][i] = -INFINITY;
            }
        }
        // softmax (max-subtracted) per row
        float m[4], l[4];
        #pragma unroll
        for (int r = 0; r < 4; r++) {
            float mm = s[r][0];
            #pragma unroll
            for (int i = 1; i < 16; i++) mm = fmaxf(mm, s[r][i]);
            #pragma unroll
            for (int off = 16; off >= 1; off >>= 1)
                mm = fmaxf(mm, __shfl_xor_sync(0xffffffffu, mm, off));
            m[r] = mm;
        }
        #pragma unroll
        for (int r = 0; r < 4; r++) {
            float sum = 0.f;
            #pragma unroll
            for (int i = 0; i < 16; i++) {
                float p = __expf(s[r][i] - m[r]);
                s[r][i] = p;
                sum += p;
            }
            #pragma unroll
            for (int off = 16; off >= 1; off >>= 1)
                sum += __shfl_xor_sync(0xffffffffu, sum, off);
            l[r] = sum;
        }
        float o[4][8];
        #pragma unroll
        for (int r = 0; r < 4; r++)
            #pragma unroll
            for (int dd = 0; dd < 8; dd++) o[r][dd] = 0.f;
        #pragma unroll
        for (int i = 0; i < 16; i++) {
            int j = lane + 32*i;
            float vd[8];
            #pragma unroll
            for (int dd = 0; dd < 8; dd++) vd[dd] = vs[dd*NN + j];
            #pragma unroll
            for (int r = 0; r < 4; r++)
                #pragma unroll
                for (int dd = 0; dd < 8; dd++) o[r][dd] += s[r][i]*vd[dd];
        }
        #pragma unroll
        for (int off = 16; off >= 1; off >>= 1)
            #pragma unroll
            for (int r = 0; r < 4; r++)
                #pragma unroll
                for (int dd = 0; dd < 8; dd++)
                    o[r][dd] += __shfl_xor_sync(0xffffffffu, o[r][dd], off);

        float linv[4];
        #pragma unroll
        for (int r = 0; r < 4; r++) linv[r] = 1.f / l[r];
        #pragma unroll
        for (int dd = 0; dd < 8; dd++)
            if (lane == dd)
                #pragma unroll
                for (int r = 0; r < 4; r++)
                    outp[(n0 + r)*8 + dd] = o[r][dd] * linv[r];
    }
}

// ---------------------------------------------------------------------------
// Kernel 3: gather + concat + residual + ReLU.
// The torch-faithful reshape means: out[b,c,t,n] reads attention scratch
// at flat offset n*384 + t*32 + (c%32) — directly, no decode.
// ---------------------------------------------------------------------------
__global__ void k_final(const float* __restrict__ x, float* __restrict__ out) {
    int bt = blockIdx.x, c = blockIdx.y;
    int n = threadIdx.x;
    int b = bt / NT, t = bt % NT;
    int cc = c & 31;
    int sel = (c < 32) ? 1 : 0;    // c<32 -> plain (blk 1), c>=32 -> geo (blk 0)
    int flat = n*384 + t*32 + cc;
    float v = d_attn[(sel*NB + b)*(4*NT*NN*8) + flat];
    int xi = ((b*64 + c)*NT + t)*NN + n;
    out[xi] = fmaxf(v + x[xi], 0.f);
}

// ---------------------------------------------------------------------------
extern "C" void kernel_launch(void* const* d_in, const int* in_sizes, int n_in,
                              void* d_out, int out_size) {
    const float* x    = (const float*)d_in[0];
    const void*  mask = d_in[1];
    const float* wp   = (const float*)d_in[2];
    const float* bp   = (const float*)d_in[3];
    WPtrs P;
    // group order: 0..2 = geo q,k,v ; 3..5 = plain q,k,v
    for (int g = 0; g < 6; g++) {
        P.w[g] = (const float*)d_in[4 + 2*g];
        P.b[g] = (const float*)d_in[5 + 2*g];
    }

    k_combine  <<<1, 256>>>(wp, bp, P);
    k_maskdetect<<<1, 256>>>(mask);
    k_maskconv <<<(NN*NN)/256, 256>>>(mask);
    k_qkv      <<<dim3(NBT, 4), 256>>>(x);
    k_attn     <<<dim3(NBT, 4, 2), 256>>>();
    k_final    <<<dim3(NBT, 64), 512>>>(x, (float*)d_out);
}

// round 3
// speedup vs baseline: 1.3074x; 1.3074x over previous
#include <cuda_runtime.h>
#include <math.h>
#include <stdint.h>

// Problem dims
#define NB 8
#define ND 64
#define NT 12
#define NN 512
#define NBT (NB*NT)            // 96
#define ATT_SCALE 0.35355339059327373f   // 8^-0.5

// Scratch (static __device__ — no allocations allowed)
__device__ float d_wc[6*64*32];            // combined weights [g][i(64)][o(32)]
__device__ float d_bc[6*32];               // combined biases  [g][o]
__device__ float d_qkv[6*NBT*32*NN];       // [g][bt][o][n]
__device__ float d_attn[2*NB*4*NT*NN*8];   // [blk][b][(h*T+t)*N*8 + n*8 + d]
__device__ unsigned int d_maskbits[16*NN]; // [word c][n] : bit i = mask[n][c*32+i]
__device__ int d_mask_mode;

struct WPtrs { const float* w[6]; const float* b[6]; };

// ---------------------------------------------------------------------------
// Kernel 0: fold proj1 into the 6 QKV projections.
// Wc[g] = WX[g] @ Wproj1  (32x64), bc[g] = WX[g] @ bproj1 + bX[g]
// ---------------------------------------------------------------------------
__global__ void k_combine(const float* __restrict__ wp, const float* __restrict__ bp, WPtrs P) {
    int tid = threadIdx.x;
    for (int idx = tid; idx < 6*64*32; idx += 256) {
        int g = idx / 2048;
        int r = idx & 2047;
        int i = r >> 5;      // input channel of x
        int o = r & 31;      // output channel
        const float* wx = P.w[g];
        float acc = 0.f;
        #pragma unroll
        for (int c = 0; c < 32; c++) acc += wx[o*32 + c] * wp[c*64 + i];
        d_wc[idx] = acc;     // layout [g][i][o]
    }
    for (int idx = tid; idx < 6*32; idx += 256) {
        int g = idx >> 5, o = idx & 31;
        const float* wx = P.w[g];
        float acc = P.b[g][o];
        for (int c = 0; c < 32; c++) acc += wx[o*32 + c] * bp[c];
        d_bc[idx] = acc;
    }
}

// ---------------------------------------------------------------------------
// Mask dtype detection (int32 / float32 / uint8 0-1 arrays distinguishable
// by word inspection), then bit-packing into transposed [word][n] layout.
// ---------------------------------------------------------------------------
__global__ void k_maskdetect(const void* __restrict__ m) {
    __shared__ int oki, okf;
    if (threadIdx.x == 0) { oki = 1; okf = 1; }
    __syncthreads();
    const unsigned int* p = (const unsigned int*)m;
    for (int idx = threadIdx.x; idx < 4096; idx += 256) {
        unsigned int v = p[idx];
        if (v != 0u && v != 1u) oki = 0;
        float f = __uint_as_float(v);
        if (f != 0.0f && f != 1.0f) okf = 0;
    }
    __syncthreads();
    if (threadIdx.x == 0) d_mask_mode = oki ? 0 : (okf ? 1 : 2);
}

__global__ void k_maskpack(const void* __restrict__ m) {
    int n = blockIdx.x;      // query row
    int j = threadIdx.x;     // key col
    int mode = d_mask_mode;
    bool v;
    if (mode == 0)      v = ((const int*)m)[n*NN + j] != 0;
    else if (mode == 1) v = ((const float*)m)[n*NN + j] != 0.0f;
    else                v = ((const unsigned char*)m)[n*NN + j] != 0;
    unsigned int word = __ballot_sync(0xffffffffu, v);
    if ((j & 31) == 0) d_maskbits[(j >> 5)*NN + n] = word;
}

// ---------------------------------------------------------------------------
// Kernel 1: QKV for both attention blocks straight from x.
// ---------------------------------------------------------------------------
__global__ __launch_bounds__(256) void k_qkv(const float* __restrict__ x) {
    __shared__ float xs[64*128];   // [ci][n]
    __shared__ float ws[64*32];    // [ci][o]
    int bt = blockIdx.x;
    int ntile = blockIdx.y;
    int b = bt / NT, t = bt % NT;
    int tid = threadIdx.x;

    for (int idx = tid; idx < 64*128; idx += 256) {
        int ci = idx >> 7, n = idx & 127;
        xs[idx] = x[((b*64 + ci)*NT + t)*NN + ntile*128 + n];
    }

    int nt = tid & 31, grp = tid >> 5;
    int n0 = nt*4, o0 = grp*4;

    for (int g = 0; g < 6; g++) {
        __syncthreads();
        for (int idx = tid; idx < 2048; idx += 256) ws[idx] = d_wc[g*2048 + idx];
        __syncthreads();

        float acc[4][4];
        #pragma unroll
        for (int i = 0; i < 4; i++) {
            float bias = d_bc[g*32 + o0 + i];
            #pragma unroll
            for (int j = 0; j < 4; j++) acc[i][j] = bias;
        }
        #pragma unroll 4
        for (int ci = 0; ci < 64; ci++) {
            float4 xv = *(const float4*)&xs[ci*128 + n0];
            float4 wv = *(const float4*)&ws[ci*32 + o0];
            float xa[4] = {xv.x, xv.y, xv.z, xv.w};
            float wa[4] = {wv.x, wv.y, wv.z, wv.w};
            #pragma unroll
            for (int i = 0; i < 4; i++)
                #pragma unroll
                for (int j = 0; j < 4; j++) acc[i][j] += wa[i]*xa[j];
        }
        #pragma unroll
        for (int i = 0; i < 4; i++) {
            float4 v = make_float4(acc[i][0], acc[i][1], acc[i][2], acc[i][3]);
            *(float4*)&d_qkv[((g*NBT + bt)*32 + o0 + i)*NN + ntile*128 + n0] = v;
        }
    }
}

// ---------------------------------------------------------------------------
// Kernel 2: attention, query-per-lane + online softmax. No shuffles.
// smem: qs/ks/vs as [n][8] = exactly 48KB static. Mask bits from global
// (32KB table shared by all CTAs -> L2-resident, coalesced LDG).
// ---------------------------------------------------------------------------
template<bool MASKED>
__device__ __forceinline__ void attn_loop(
    const float* __restrict__ qs, const float* __restrict__ ks,
    const float* __restrict__ vs, float* __restrict__ outp)
{
    int tid = threadIdx.x, lane = tid & 31, w = tid >> 5;
    for (int set = w; set < 16; set += 8) {
        int n = set*32 + lane;
        const float4 q0 = *(const float4*)&qs[n*8];
        const float4 q1 = *(const float4*)&qs[n*8 + 4];
        float mx = -1e30f, l = 0.f;
        float o0=0,o1=0,o2=0,o3=0,o4=0,o5=0,o6=0,o7=0;

        #pragma unroll 1
        for (int c32 = 0; c32 < 16; c32++) {
            unsigned int bits = 0;
            if (MASKED) bits = __ldg(&d_maskbits[c32*NN + n]);
            #pragma unroll
            for (int half = 0; half < 2; half++) {
                int jb = c32*32 + half*16;
                float s[16];
                #pragma unroll
                for (int i = 0; i < 16; i++) {
                    const float4 k0 = *(const float4*)&ks[(jb+i)*8];
                    const float4 k1 = *(const float4*)&ks[(jb+i)*8 + 4];
                    float a = q0.x*k0.x;
                    a = fmaf(q0.y, k0.y, a); a = fmaf(q0.z, k0.z, a); a = fmaf(q0.w, k0.w, a);
                    a = fmaf(q1.x, k1.x, a); a = fmaf(q1.y, k1.y, a);
                    a = fmaf(q1.z, k1.z, a); a = fmaf(q1.w, k1.w, a);
                    s[i] = a;
                }
                if (MASKED) {
                    unsigned int b = bits >> (half*16);
                    #pragma unroll
                    for (int i = 0; i < 16; i++)
                        if ((b >> i) & 1u) s[i] = -INFINITY;
                }
                float cm = s[0];
                #pragma unroll
                for (int i = 1; i < 16; i++) cm = fmaxf(cm, s[i]);
                float nm = fmaxf(fmaxf(mx, cm), -1e30f);  // clamp: avoids -inf - -inf
                float corr = __expf(mx - nm);
                mx = nm;
                l *= corr;
                o0*=corr; o1*=corr; o2*=corr; o3*=corr;
                o4*=corr; o5*=corr; o6*=corr; o7*=corr;
                #pragma unroll
                for (int i = 0; i < 16; i++) {
                    float p = __expf(s[i] - nm);
                    l += p;
                    const float4 v0 = *(const float4*)&vs[(jb+i)*8];
                    const float4 v1 = *(const float4*)&vs[(jb+i)*8 + 4];
                    o0 = fmaf(p, v0.x, o0); o1 = fmaf(p, v0.y, o1);
                    o2 = fmaf(p, v0.z, o2); o3 = fmaf(p, v0.w, o3);
                    o4 = fmaf(p, v1.x, o4); o5 = fmaf(p, v1.y, o5);
                    o6 = fmaf(p, v1.z, o6); o7 = fmaf(p, v1.w, o7);
                }
            }
        }
        float inv = 1.f / l;
        float4 r0 = make_float4(o0*inv, o1*inv, o2*inv, o3*inv);
        float4 r1 = make_float4(o4*inv, o5*inv, o6*inv, o7*inv);
        *(float4*)&outp[n*8]     = r0;
        *(float4*)&outp[n*8 + 4] = r1;
    }
}

__global__ __launch_bounds__(256) void k_attn2() {
    __shared__ float qs[NN*8];   // [n][8]
    __shared__ float ks[NN*8];
    __shared__ float vs[NN*8];   // total: exactly 48KB
    int bt = blockIdx.x, h = blockIdx.y, blk = blockIdx.z;
    int gbase = blk * 3;       // blk 0 -> geo (masked); blk 1 -> plain
    int tid = threadIdx.x;

    for (int idx = tid; idx < 4096; idx += 256) {
        int dd = idx >> 9, n = idx & 511;
        int c = h*8 + dd;
        qs[n*8 + dd] = d_qkv[(( gbase   *NBT + bt)*32 + c)*NN + n] * ATT_SCALE;
        ks[n*8 + dd] = d_qkv[(((gbase+1)*NBT + bt)*32 + c)*NN + n];
        vs[n*8 + dd] = d_qkv[(((gbase+2)*NBT + bt)*32 + c)*NN + n];
    }
    __syncthreads();

    int b = bt / NT, t = bt % NT;
    float* outp = d_attn + (blk*NB + b)*(4*NT*NN*8) + (h*NT + t)*(NN*8);
    if (blk == 0) attn_loop<true >(qs, ks, vs, outp);
    else          attn_loop<false>(qs, ks, vs, outp);
}

// ---------------------------------------------------------------------------
// Kernel 3: gather + concat + residual + ReLU.
// ---------------------------------------------------------------------------
__global__ void k_final(const float* __restrict__ x, float* __restrict__ out) {
    int bt = blockIdx.x, c = blockIdx.y;
    int n = threadIdx.x;
    int b = bt / NT, t = bt % NT;
    int cc = c & 31;
    int sel = (c < 32) ? 1 : 0;    // c<32 -> plain (blk 1), c>=32 -> geo (blk 0)
    int flat = n*384 + t*32 + cc;
    float v = d_attn[(sel*NB + b)*(4*NT*NN*8) + flat];
    int xi = ((b*64 + c)*NT + t)*NN + n;
    out[xi] = fmaxf(v + x[xi], 0.f);
}

// ---------------------------------------------------------------------------
extern "C" void kernel_launch(void* const* d_in, const int* in_sizes, int n_in,
                              void* d_out, int out_size) {
    const float* x    = (const float*)d_in[0];
    const void*  mask = d_in[1];
    const float* wp   = (const float*)d_in[2];
    const float* bp   = (const float*)d_in[3];
    WPtrs P;
    for (int g = 0; g < 6; g++) {
        P.w[g] = (const float*)d_in[4 + 2*g];
        P.b[g] = (const float*)d_in[5 + 2*g];
    }

    k_combine   <<<1, 256>>>(wp, bp, P);
    k_maskdetect<<<1, 256>>>(mask);
    k_maskpack  <<<NN, NN>>>(mask);
    k_qkv       <<<dim3(NBT, 4), 256>>>(x);
    k_attn2     <<<dim3(NBT, 4, 2), 256>>>();
    k_final     <<<dim3(NBT, 64), 512>>>(x, (float*)d_out);
}

// round 4
// speedup vs baseline: 1.3639x; 1.0432x over previous
#include <cuda_runtime.h>
#include <math.h>
#include <stdint.h>

// Problem dims
#define NB 8
#define ND 64
#define NT 12
#define NN 512
#define NBT (NB*NT)            // 96
#define ATT_SCALE 0.35355339059327373f   // 8^-0.5
#define LOG2E 1.4426950408889634f

typedef unsigned long long ull;

// Scratch (static __device__ — no allocations allowed)
__device__ float d_wc[6*64*32];            // combined weights [g][i(64)][o(32)]
__device__ float d_bc[6*32];               // combined biases  [g][o]
__device__ float d_qkv[6*NBT*32*NN];       // [g][bt][o][n]
__device__ float d_attn[2*NB*4*NT*NN*8];   // [blk][b][(h*T+t)*N*8 + n*8 + d]
__device__ unsigned int d_maskbits[16*NN]; // [word c][n] : bit i = mask[n][c*32+i]
__device__ int d_mask_mode;

struct WPtrs { const float* w[6]; const float* b[6]; };

// ---------------- f32x2 / ex2 helpers ----------------
__device__ __forceinline__ ull pack2(float a, float b) {
    ull r; asm("mov.b64 %0, {%1, %2};" : "=l"(r) : "f"(a), "f"(b)); return r;
}
__device__ __forceinline__ void unpack2(ull v, float& a, float& b) {
    asm("mov.b64 {%0, %1}, %2;" : "=f"(a), "=f"(b) : "l"(v));
}
__device__ __forceinline__ ull fma2(ull a, ull b, ull c) {
    ull r; asm("fma.rn.f32x2 %0, %1, %2, %3;" : "=l"(r) : "l"(a), "l"(b), "l"(c)); return r;
}
__device__ __forceinline__ ull add2(ull a, ull b) {
    ull r; asm("add.rn.f32x2 %0, %1, %2;" : "=l"(r) : "l"(a), "l"(b)); return r;
}
__device__ __forceinline__ float ex2f(float x) {
    float r; asm("ex2.approx.f32 %0, %1;" : "=f"(r) : "f"(x)); return r;
}
template<int OFF>
__device__ __forceinline__ void lds_v2o(unsigned sa, ull& a, ull& b) {
    asm("ld.shared.v2.b64 {%0, %1}, [%2+%3];" : "=l"(a), "=l"(b) : "r"(sa), "n"(OFF));
}

// ---------------------------------------------------------------------------
// Kernel 0: fold proj1 into the 6 QKV projections.
// Q-groups (0 and 3) additionally absorb ATT_SCALE*log2(e) so attention's
// softmax argument is directly in the exp2 domain.
// ---------------------------------------------------------------------------
__global__ void k_combine(const float* __restrict__ wp, const float* __restrict__ bp, WPtrs P) {
    int tid = threadIdx.x;
    for (int idx = tid; idx < 6*64*32; idx += 256) {
        int g = idx / 2048;
        int r = idx & 2047;
        int i = r >> 5;      // input channel of x
        int o = r & 31;      // output channel
        const float* wx = P.w[g];
        float acc = 0.f;
        #pragma unroll
        for (int c = 0; c < 32; c++) acc += wx[o*32 + c] * wp[c*64 + i];
        if (g == 0 || g == 3) acc *= ATT_SCALE * LOG2E;
        d_wc[idx] = acc;     // layout [g][i][o]
    }
    for (int idx = tid; idx < 6*32; idx += 256) {
        int g = idx >> 5, o = idx & 31;
        const float* wx = P.w[g];
        float acc = P.b[g][o];
        for (int c = 0; c < 32; c++) acc += wx[o*32 + c] * bp[c];
        if (g == 0 || g == 3) acc *= ATT_SCALE * LOG2E;
        d_bc[idx] = acc;
    }
}

// ---------------------------------------------------------------------------
// Mask dtype detection + bit-packing to transposed [word][n] layout.
// ---------------------------------------------------------------------------
__global__ void k_maskdetect(const void* __restrict__ m) {
    __shared__ int oki, okf;
    if (threadIdx.x == 0) { oki = 1; okf = 1; }
    __syncthreads();
    const unsigned int* p = (const unsigned int*)m;
    for (int idx = threadIdx.x; idx < 4096; idx += 256) {
        unsigned int v = p[idx];
        if (v != 0u && v != 1u) oki = 0;
        float f = __uint_as_float(v);
        if (f != 0.0f && f != 1.0f) okf = 0;
    }
    __syncthreads();
    if (threadIdx.x == 0) d_mask_mode = oki ? 0 : (okf ? 1 : 2);
}

__global__ void k_maskpack(const void* __restrict__ m) {
    int n = blockIdx.x;      // query row
    int j = threadIdx.x;     // key col
    int mode = d_mask_mode;
    bool v;
    if (mode == 0)      v = ((const int*)m)[n*NN + j] != 0;
    else if (mode == 1) v = ((const float*)m)[n*NN + j] != 0.0f;
    else                v = ((const unsigned char*)m)[n*NN + j] != 0;
    unsigned int word = __ballot_sync(0xffffffffu, v);
    if ((j & 31) == 0) d_maskbits[(j >> 5)*NN + n] = word;
}

// ---------------------------------------------------------------------------
// Kernel 1: QKV for both attention blocks straight from x. (unchanged)
// ---------------------------------------------------------------------------
__global__ __launch_bounds__(256) void k_qkv(const float* __restrict__ x) {
    __shared__ float xs[64*128];   // [ci][n]
    __shared__ float ws[64*32];    // [ci][o]
    int bt = blockIdx.x;
    int ntile = blockIdx.y;
    int b = bt / NT, t = bt % NT;
    int tid = threadIdx.x;

    for (int idx = tid; idx < 64*128; idx += 256) {
        int ci = idx >> 7, n = idx & 127;
        xs[idx] = x[((b*64 + ci)*NT + t)*NN + ntile*128 + n];
    }

    int nt = tid & 31, grp = tid >> 5;
    int n0 = nt*4, o0 = grp*4;

    for (int g = 0; g < 6; g++) {
        __syncthreads();
        for (int idx = tid; idx < 2048; idx += 256) ws[idx] = d_wc[g*2048 + idx];
        __syncthreads();

        float acc[4][4];
        #pragma unroll
        for (int i = 0; i < 4; i++) {
            float bias = d_bc[g*32 + o0 + i];
            #pragma unroll
            for (int j = 0; j < 4; j++) acc[i][j] = bias;
        }
        #pragma unroll 4
        for (int ci = 0; ci < 64; ci++) {
            float4 xv = *(const float4*)&xs[ci*128 + n0];
            float4 wv = *(const float4*)&ws[ci*32 + o0];
            float xa[4] = {xv.x, xv.y, xv.z, xv.w};
            float wa[4] = {wv.x, wv.y, wv.z, wv.w};
            #pragma unroll
            for (int i = 0; i < 4; i++)
                #pragma unroll
                for (int j = 0; j < 4; j++) acc[i][j] += wa[i]*xa[j];
        }
        #pragma unroll
        for (int i = 0; i < 4; i++) {
            float4 v = make_float4(acc[i][0], acc[i][1], acc[i][2], acc[i][3]);
            *(float4*)&d_qkv[((g*NBT + bt)*32 + o0 + i)*NN + ntile*128 + n0] = v;
        }
    }
}

// ---------------------------------------------------------------------------
// Kernel 2: attention. 128 threads (4 warps x 4 query-sets), 32KB smem.
// K/V in native [d][n] layout -> LDS.128 gives 4 keys' d-values = two f32x2
// operands. Packed QK + packed PV + one-pass exp2 softmax (no running max:
// q pre-scaled into log2-domain, masked scores -> -inf -> ex2 -> 0).
// ---------------------------------------------------------------------------
#define NINF __int_as_float(0xff800000)

#define QK_STEP(d) { ull k01, k23; lds_v2o<(d)*2048>(kaddr, k01, k23); \
                     acc01 = fma2(q2[d], k01, acc01); acc23 = fma2(q2[d], k23, acc23); }
#define PV_STEP(d) { ull v01, v23; lds_v2o<(d)*2048>(vaddr, v01, v23); \
                     o2[d] = fma2(p01, v01, o2[d]); o2[d] = fma2(p23, v23, o2[d]); }

template<bool MASKED>
__device__ __forceinline__ void attn_loop3(
    unsigned ksb, unsigned vsb, const float* __restrict__ qg, float* __restrict__ outp)
{
    int tid = threadIdx.x, lane = tid & 31, w = tid >> 5;
    for (int set = w*4; set < w*4 + 4; set++) {
        int n = set*32 + lane;
        ull q2[8];
        #pragma unroll
        for (int d = 0; d < 8; d++) {
            float qv = __ldg(&qg[d*NN + n]);
            q2[d] = pack2(qv, qv);
        }
        ull o2[8];
        #pragma unroll
        for (int d = 0; d < 8; d++) o2[d] = 0ull;
        ull l2 = 0ull;

        #pragma unroll 1
        for (int c32 = 0; c32 < 16; c32++) {
            unsigned int bits = 0;
            if (MASKED) bits = __ldg(&d_maskbits[c32*NN + n]);
            unsigned kaddr = ksb + (c32*32)*4;
            unsigned vaddr = vsb + (c32*32)*4;
            #pragma unroll 2
            for (int g4 = 0; g4 < 8; g4++) {
                ull acc01 = 0ull, acc23 = 0ull;
                QK_STEP(0) QK_STEP(1) QK_STEP(2) QK_STEP(3)
                QK_STEP(4) QK_STEP(5) QK_STEP(6) QK_STEP(7)
                float s0, s1, s2, s3;
                unpack2(acc01, s0, s1);
                unpack2(acc23, s2, s3);
                if (MASKED) {
                    unsigned int bq = bits >> (g4*4);
                    if (bq & 1u) s0 = NINF;
                    if (bq & 2u) s1 = NINF;
                    if (bq & 4u) s2 = NINF;
                    if (bq & 8u) s3 = NINF;
                }
                float p0 = ex2f(s0), p1 = ex2f(s1), p2 = ex2f(s2), p3 = ex2f(s3);
                ull p01 = pack2(p0, p1), p23 = pack2(p2, p3);
                l2 = add2(l2, p01);
                l2 = add2(l2, p23);
                PV_STEP(0) PV_STEP(1) PV_STEP(2) PV_STEP(3)
                PV_STEP(4) PV_STEP(5) PV_STEP(6) PV_STEP(7)
                kaddr += 16;
                vaddr += 16;
            }
        }
        float la, lb;
        unpack2(l2, la, lb);
        float inv = 1.f / (la + lb);
        float o[8];
        #pragma unroll
        for (int d = 0; d < 8; d++) {
            float a, b;
            unpack2(o2[d], a, b);
            o[d] = (a + b) * inv;
        }
        *(float4*)&outp[n*8]     = make_float4(o[0], o[1], o[2], o[3]);
        *(float4*)&outp[n*8 + 4] = make_float4(o[4], o[5], o[6], o[7]);
    }
}

__global__ __launch_bounds__(128) void k_attn3() {
    __shared__ float ks[8*NN];   // [d][n] — native d_qkv layout
    __shared__ float vs[8*NN];   // 32KB total
    int bt = blockIdx.x, h = blockIdx.y, blk = blockIdx.z;
    int gbase = blk * 3;         // blk 0 -> geo (masked); blk 1 -> plain
    int tid = threadIdx.x;

    const float* qg = d_qkv + (( gbase   *NBT + bt)*32 + h*8)*NN;
    const float* kg = d_qkv + (((gbase+1)*NBT + bt)*32 + h*8)*NN;
    const float* vg = d_qkv + (((gbase+2)*NBT + bt)*32 + h*8)*NN;

    // straight float4 copy — K/V already in the [d][n] layout we want
    {
        const float4* kg4 = (const float4*)kg;
        const float4* vg4 = (const float4*)vg;
        float4* ks4 = (float4*)ks;
        float4* vs4 = (float4*)vs;
        for (int i = tid; i < 1024; i += 128) { ks4[i] = kg4[i]; vs4[i] = vg4[i]; }
    }
    __syncthreads();

    unsigned ksb = (unsigned)__cvta_generic_to_shared(ks);
    unsigned vsb = (unsigned)__cvta_generic_to_shared(vs);

    int b = bt / NT, t = bt % NT;
    float* outp = d_attn + (blk*NB + b)*(4*NT*NN*8) + (h*NT + t)*(NN*8);
    if (blk == 0) attn_loop3<true >(ksb, vsb, qg, outp);
    else          attn_loop3<false>(ksb, vsb, qg, outp);
}

// ---------------------------------------------------------------------------
// Kernel 3: gather + concat + residual + ReLU. (unchanged)
// ---------------------------------------------------------------------------
__global__ void k_final(const float* __restrict__ x, float* __restrict__ out) {
    int bt = blockIdx.x, c = blockIdx.y;
    int n = threadIdx.x;
    int b = bt / NT, t = bt % NT;
    int cc = c & 31;
    int sel = (c < 32) ? 1 : 0;    // c<32 -> plain (blk 1), c>=32 -> geo (blk 0)
    int flat = n*384 + t*32 + cc;
    float v = d_attn[(sel*NB + b)*(4*NT*NN*8) + flat];
    int xi = ((b*64 + c)*NT + t)*NN + n;
    out[xi] = fmaxf(v + x[xi], 0.f);
}

// ---------------------------------------------------------------------------
extern "C" void kernel_launch(void* const* d_in, const int* in_sizes, int n_in,
                              void* d_out, int out_size) {
    const float* x    = (const float*)d_in[0];
    const void*  mask = d_in[1];
    const float* wp   = (const float*)d_in[2];
    const float* bp   = (const float*)d_in[3];
    WPtrs P;
    for (int g = 0; g < 6; g++) {
        P.w[g] = (const float*)d_in[4 + 2*g];
        P.b[g] = (const float*)d_in[5 + 2*g];
    }

    k_combine   <<<1, 256>>>(wp, bp, P);
    k_maskdetect<<<1, 256>>>(mask);
    k_maskpack  <<<NN, NN>>>(mask);
    k_qkv       <<<dim3(NBT, 4), 256>>>(x);
    k_attn3     <<<dim3(NBT, 4, 2), 128>>>();
    k_final     <<<dim3(NBT, 64), 512>>>(x, (float*)d_out);
}

// round 6
// speedup vs baseline: 1.8988x; 1.3922x over previous
#include <cuda_runtime.h>
#include <cuda_bf16.h>
#include <math.h>
#include <stdint.h>

// Problem dims
#define NB 8
#define NT 12
#define NN 512
#define NBT 96
#define ATT_SCALE 0.35355339059327373f   // 8^-0.5
#define LOG2E 1.4426950408889634f
#define NINF __int_as_float(0xff800000)

// Scratch (static __device__ — no allocations allowed)
__device__ float d_wc[6*64*32];                 // combined weights [g][i(64)][o(32)]
__device__ float d_bc[6*32];                    // combined biases  [g][o]
__device__ __nv_bfloat16 d_qt[4*NBT*4*NN*8];    // [qi][bt][h][n][d]  (q/k, transposed)
__device__ __nv_bfloat16 d_vt[2*NBT*4*8*NN];    // [vi][bt][h][d][n]  (v, native)
__device__ float d_attn[2*NB*4*NT*NN*8];        // [blk][b][h][t][n][d] flat
__device__ unsigned int d_maskw[NN*16];         // [n][word] bit j = mask[n][word*32+j]
__device__ int d_mask_mode;

struct WPtrs { const float* w[6]; const float* b[6]; };

// ---------------- helpers ----------------
__device__ __forceinline__ float ex2f(float x) {
    float r; asm("ex2.approx.f32 %0, %1;" : "=f"(r) : "f"(x)); return r;
}
__device__ __forceinline__ unsigned bf2(float lo, float hi) {
    unsigned r; asm("cvt.rn.bf16x2.f32 %0, %1, %2;" : "=r"(r) : "f"(hi), "f"(lo)); return r;
}
__device__ __forceinline__ unsigned lds32(unsigned addr) {
    unsigned v; asm("ld.shared.b32 %0, [%1];" : "=r"(v) : "r"(addr)); return v;
}
__device__ __forceinline__ void mma_bf16(
    float& d0, float& d1, float& d2, float& d3,
    unsigned a0, unsigned a1, unsigned b0,
    float c0, float c1, float c2, float c3)
{
    asm("mma.sync.aligned.m16n8k8.row.col.f32.bf16.bf16.f32 "
        "{%0,%1,%2,%3},{%4,%5},{%6},{%7,%8,%9,%10};"
        : "=f"(d0), "=f"(d1), "=f"(d2), "=f"(d3)
        : "r"(a0), "r"(a1), "r"(b0), "f"(c0), "f"(c1), "f"(c2), "f"(c3));
}

// ---------------------------------------------------------------------------
// Kernel 0 (fused): block 0 = weight folding, block 1 = mask dtype detection.
// Q-groups (0,3) absorb ATT_SCALE*log2(e) -> scores land in exp2 domain.
// ---------------------------------------------------------------------------
__global__ void k_setup(const float* __restrict__ wp, const float* __restrict__ bp,
                        WPtrs P, const void* __restrict__ m) {
    int tid = threadIdx.x;
    if (blockIdx.x == 0) {
        for (int idx = tid; idx < 6*64*32; idx += 256) {
            int g = idx / 2048;
            int r = idx & 2047;
            int i = r >> 5, o = r & 31;
            const float* wx = P.w[g];
            float acc = 0.f;
            #pragma unroll
            for (int c = 0; c < 32; c++) acc += wx[o*32 + c] * wp[c*64 + i];
            if (g == 0 || g == 3) acc *= ATT_SCALE * LOG2E;
            d_wc[idx] = acc;
        }
        for (int idx = tid; idx < 6*32; idx += 256) {
            int g = idx >> 5, o = idx & 31;
            const float* wx = P.w[g];
            float acc = P.b[g][o];
            for (int c = 0; c < 32; c++) acc += wx[o*32 + c] * bp[c];
            if (g == 0 || g == 3) acc *= ATT_SCALE * LOG2E;
            d_bc[idx] = acc;
        }
    } else {
        __shared__ int oki, okf;
        if (tid == 0) { oki = 1; okf = 1; }
        __syncthreads();
        const unsigned int* p = (const unsigned int*)m;
        for (int idx = tid; idx < 4096; idx += 256) {
            unsigned int v = p[idx];
            if (v != 0u && v != 1u) oki = 0;
            float f = __uint_as_float(v);
            if (f != 0.0f && f != 1.0f) okf = 0;
        }
        __syncthreads();
        if (tid == 0) d_mask_mode = oki ? 0 : (okf ? 1 : 2);
    }
}

// ---------------------------------------------------------------------------
// Mask bit-pack to per-row words: d_maskw[n][w], bit j = mask[n][w*32+j].
// ---------------------------------------------------------------------------
__global__ void k_maskpack(const void* __restrict__ m) {
    int n = blockIdx.x;
    int j = threadIdx.x;
    int mode = d_mask_mode;
    bool v;
    if (mode == 0)      v = ((const int*)m)[n*NN + j] != 0;
    else if (mode == 1) v = ((const float*)m)[n*NN + j] != 0.0f;
    else                v = ((const unsigned char*)m)[n*NN + j] != 0;
    unsigned int word = __ballot_sync(0xffffffffu, v);
    if ((j & 31) == 0) d_maskw[n*16 + (j >> 5)] = word;
}

// ---------------------------------------------------------------------------
// Kernel 1: QKV from x, emitting bf16 in MMA-friendly layouts.
//   q/k (g 0,1,3,4) -> d_qt[qi][bt][h][n][8]   (transposed per head)
//   v   (g 2,5)     -> d_vt[vi][bt][h][8][n]   (native per head)
// ---------------------------------------------------------------------------
__global__ __launch_bounds__(256) void k_qkv(const float* __restrict__ x) {
    __shared__ float xs[64*128];   // [ci][n]
    __shared__ float ws[64*32];    // [ci][o]
    int bt = blockIdx.x;
    int ntile = blockIdx.y;
    int b = bt / NT, t = bt % NT;
    int tid = threadIdx.x;

    for (int idx = tid; idx < 64*128; idx += 256) {
        int ci = idx >> 7, n = idx & 127;
        xs[idx] = x[((b*64 + ci)*NT + t)*NN + ntile*128 + n];
    }

    int nt = tid & 31, grp = tid >> 5;
    int n0 = nt*4, o0 = grp*4;
    int h = o0 >> 3;

    for (int g = 0; g < 6; g++) {
        __syncthreads();
        for (int idx = tid; idx < 2048; idx += 256) ws[idx] = d_wc[g*2048 + idx];
        __syncthreads();

        float acc[4][4];
        #pragma unroll
        for (int i = 0; i < 4; i++) {
            float bias = d_bc[g*32 + o0 + i];
            #pragma unroll
            for (int j = 0; j < 4; j++) acc[i][j] = bias;
        }
        #pragma unroll 4
        for (int ci = 0; ci < 64; ci++) {
            float4 xv = *(const float4*)&xs[ci*128 + n0];
            float4 wv = *(const float4*)&ws[ci*32 + o0];
            float xa[4] = {xv.x, xv.y, xv.z, xv.w};
            float wa[4] = {wv.x, wv.y, wv.z, wv.w};
            #pragma unroll
            for (int i = 0; i < 4; i++)
                #pragma unroll
                for (int j = 0; j < 4; j++) acc[i][j] += wa[i]*xa[j];
        }

        if (g == 2 || g == 5) {
            // V: [vi][bt][h][d][n], 4 d-rows x 4 consecutive n
            int vi = (g == 5) ? 1 : 0;
            int dd = o0 & 7;
            #pragma unroll
            for (int i = 0; i < 4; i++) {
                unsigned lo = bf2(acc[i][0], acc[i][1]);
                unsigned hi = bf2(acc[i][2], acc[i][3]);
                long long base = ((((long long)vi*NBT + bt)*4 + h)*8 + dd + i)*NN
                                 + ntile*128 + n0;
                *(uint2*)((__nv_bfloat16*)d_vt + base) = make_uint2(lo, hi);
            }
        } else {
            // Q/K transposed: [qi][bt][h][n][8], per n write d0..d0+3
            // group->slot: 0(geo q)->0, 1(geo k)->1, 3(plain q)->2, 4(plain k)->3
            int qi = (g < 2) ? g : g - 1;
            int d0 = o0 & 7;                  // 0 or 4
            #pragma unroll
            for (int j = 0; j < 4; j++) {
                unsigned lo = bf2(acc[0][j], acc[1][j]);
                unsigned hi = bf2(acc[2][j], acc[3][j]);
                int n = ntile*128 + n0 + j;
                long long base = ((((long long)qi*NBT + bt)*4 + h)*NN + n)*8 + d0;
                *(uint2*)((__nv_bfloat16*)d_qt + base) = make_uint2(lo, hi);
            }
        }
    }
}

// ---------------------------------------------------------------------------
// Kernel 2: flash attention via mma.sync m16n8k8 bf16.
// Per CTA: (bt, h, blk). 4 warps x 8 tiles of 16 queries; 64 key-chunks of 8.
// QK D-frag layout == PV A-frag layout -> shuffle-free exp->P conversion.
// One-pass exp2 softmax (q pre-scaled to log2 domain; masked -> -inf -> 0).
// Writes normalized output to d_attn scratch; k_final does the torch-faithful
// scrambled gather + residual + relu (proven in R1-R3).
// ---------------------------------------------------------------------------
#define VSTRIDE 1040   // bytes; 1040/4 = 260 ≡ 4 (mod 32) -> banks (4g+tq) all distinct

template<bool MASKED>
__device__ __forceinline__ void attn_mma(
    unsigned ksb, unsigned vsb,
    const unsigned* __restrict__ qgu,
    float* __restrict__ outp)
{
    int tid = threadIdx.x, lane = tid & 31, wid = tid >> 5;
    int g = lane >> 2, tq = lane & 3;

    for (int tile = wid; tile < 32; tile += 4) {
        int qbase = tile * 16;
        int r0 = qbase + g, r1 = r0 + 8;
        unsigned qa0 = __ldg(qgu + r0*4 + tq);
        unsigned qa1 = __ldg(qgu + r1*4 + tq);

        float o0 = 0.f, o1 = 0.f, o2 = 0.f, o3 = 0.f;
        float l0 = 0.f, l1 = 0.f;
        unsigned kaddr = ksb + g*16 + tq*4;
        unsigned vaddr = vsb + g*VSTRIDE + tq*4;

        #pragma unroll 1
        for (int cw = 0; cw < 16; cw++) {
            unsigned mw0 = 0, mw1 = 0;
            if (MASKED) {
                mw0 = __ldg(&d_maskw[r0*16 + cw]);
                mw1 = __ldg(&d_maskw[r1*16 + cw]);
            }
            #pragma unroll
            for (int sub = 0; sub < 4; sub++) {
                unsigned kb = lds32(kaddr); kaddr += 128;
                float s0, s1, s2, s3;
                mma_bf16(s0, s1, s2, s3, qa0, qa1, kb, 0.f, 0.f, 0.f, 0.f);
                if (MASKED) {
                    unsigned b0 = mw0 >> (sub*8 + tq*2);
                    unsigned b1 = mw1 >> (sub*8 + tq*2);
                    if (b0 & 1u) s0 = NINF;
                    if (b0 & 2u) s1 = NINF;
                    if (b1 & 1u) s2 = NINF;
                    if (b1 & 2u) s3 = NINF;
                }
                float p0 = ex2f(s0), p1 = ex2f(s1), p2 = ex2f(s2), p3 = ex2f(s3);
                l0 += p0 + p1;
                l1 += p2 + p3;
                unsigned pa0 = bf2(p0, p1);
                unsigned pa1 = bf2(p2, p3);
                unsigned vb = lds32(vaddr); vaddr += 16;
                mma_bf16(o0, o1, o2, o3, pa0, pa1, vb, o0, o1, o2, o3);
            }
        }
        // full row sums live across the 4 lanes of this group (xor 1 and 2)
        l0 += __shfl_xor_sync(0xffffffffu, l0, 1);
        l0 += __shfl_xor_sync(0xffffffffu, l0, 2);
        l1 += __shfl_xor_sync(0xffffffffu, l1, 1);
        l1 += __shfl_xor_sync(0xffffffffu, l1, 2);
        float inv0 = 1.f / l0, inv1 = 1.f / l1;

        // o0 = O[r0][2tq], o1 = O[r0][2tq+1], o2 = O[r1][2tq], o3 = O[r1][2tq+1]
        *(float2*)&outp[r0*8 + 2*tq] = make_float2(o0*inv0, o1*inv0);
        *(float2*)&outp[r1*8 + 2*tq] = make_float2(o2*inv1, o3*inv1);
    }
}

__global__ __launch_bounds__(128) void k_attn4() {
    __shared__ __align__(16) unsigned char ksm[NN*16];       // K [n][8] bf16, 8KB
    __shared__ __align__(16) unsigned char vsm[8*VSTRIDE];   // V [d][n] bf16, padded
    int bt = blockIdx.x, h = blockIdx.y, blk = blockIdx.z;
    int tid = threadIdx.x;

    int qi = blk ? 2 : 0;   // blk0(geo)->slot 0, blk1(plain)->slot 2
    int ki = blk ? 3 : 1;
    int vi = blk ? 1 : 0;

    const __nv_bfloat16* qg = d_qt + ((((long long)qi*NBT + bt)*4 + h)*NN)*8;
    const __nv_bfloat16* kg = d_qt + ((((long long)ki*NBT + bt)*4 + h)*NN)*8;
    const __nv_bfloat16* vg = d_vt + ((((long long)vi*NBT + bt)*4 + h)*8)*NN;

    {
        const uint4* kg4 = (const uint4*)kg;
        const uint4* vg4 = (const uint4*)vg;
        uint4* ks4 = (uint4*)ksm;
        for (int i = tid; i < 512; i += 128) {
            ks4[i] = kg4[i];
            uint4 v = vg4[i];
            int r = i >> 6, c = i & 63;
            *(uint4*)(vsm + r*VSTRIDE + c*16) = v;
        }
    }
    __syncthreads();

    unsigned ksb = (unsigned)__cvta_generic_to_shared(ksm);
    unsigned vsb = (unsigned)__cvta_generic_to_shared(vsm);
    int b = bt / NT, t = bt % NT;
    float* outp = d_attn + (blk*NB + b)*(4*NT*NN*8) + (h*NT + t)*(NN*8);

    if (blk == 0) attn_mma<true >(ksb, vsb, (const unsigned*)qg, outp);
    else          attn_mma<false>(ksb, vsb, (const unsigned*)qg, outp);
}

// ---------------------------------------------------------------------------
// Kernel 3: torch-faithful scrambled gather + concat + residual + ReLU.
// out[b,c,t,n] reads attn-flat at n*384 + t*32 + (c%31+1... c&31). (R1-R3 proven)
// ---------------------------------------------------------------------------
__global__ void k_final(const float* __restrict__ x, float* __restrict__ out) {
    int bt = blockIdx.x, c = blockIdx.y;
    int n = threadIdx.x;
    int b = bt / NT, t = bt % NT;
    int cc = c & 31;
    int sel = (c < 32) ? 1 : 0;    // c<32 -> plain (blk 1), c>=32 -> geo (blk 0)
    int flat = n*384 + t*32 + cc;
    float v = d_attn[(sel*NB + b)*(4*NT*NN*8) + flat];
    int xi = ((b*64 + c)*NT + t)*NN + n;
    out[xi] = fmaxf(v + x[xi], 0.f);
}

// ---------------------------------------------------------------------------
extern "C" void kernel_launch(void* const* d_in, const int* in_sizes, int n_in,
                              void* d_out, int out_size) {
    const float* x    = (const float*)d_in[0];
    const void*  mask = d_in[1];
    const float* wp   = (const float*)d_in[2];
    const float* bp   = (const float*)d_in[3];
    WPtrs P;
    for (int g = 0; g < 6; g++) {
        P.w[g] = (const float*)d_in[4 + 2*g];
        P.b[g] = (const float*)d_in[5 + 2*g];
    }

    k_setup   <<<2, 256>>>(wp, bp, P, mask);
    k_maskpack<<<NN, NN>>>(mask);
    k_qkv     <<<dim3(NBT, 4), 256>>>(x);
    k_attn4   <<<dim3(NBT, 4, 2), 128>>>();
    k_final   <<<dim3(NBT, 64), 512>>>(x, (float*)d_out);
}

// round 8
// speedup vs baseline: 4.6178x; 2.4319x over previous
#include <cuda_runtime.h>
#include <cuda_bf16.h>
#include <math.h>
#include <stdint.h>

// Problem dims
#define NB 8
#define NT 12
#define NN 512
#define NBT 96
#define ATT_SCALE 0.35355339059327373f   // 8^-0.5
#define LOG2E 1.4426950408889634f
#define NINF __int_as_float(0xff800000)
#define ONESBF 0x3F803F80u               // bf16 1.0 x2

// Scratch (static __device__ — no allocations allowed)
__device__ float d_wc[6*64*32];                 // combined weights [g][i(64)][o(32)]
__device__ float d_bc[6*32];                    // combined biases  [g][o]
__device__ __nv_bfloat16 d_qt[4*NBT*4*NN*8];    // [qi][bt][h][n][d]  (q/k, transposed)
__device__ __nv_bfloat16 d_vt[2*NBT*4*8*NN];    // [vi][bt][h][d][n]  (v, native)
__device__ float d_attn[2*NB*4*NT*NN*8];        // [blk][b][h][t][n][d] flat
__device__ unsigned int d_maskw[NN*16];         // [n][word] bit j = mask[n][word*32+j]
__device__ int d_mask_mode;

struct WPtrs { const float* w[6]; const float* b[6]; };

// ---------------- helpers ----------------
__device__ __forceinline__ float ex2f(float x) {
    float r; asm("ex2.approx.f32 %0, %1;" : "=f"(r) : "f"(x)); return r;
}
__device__ __forceinline__ float rcpf(float x) {
    float r; asm("rcp.approx.f32 %0, %1;" : "=f"(r) : "f"(x)); return r;
}
__device__ __forceinline__ unsigned bf2(float lo, float hi) {
    unsigned r; asm("cvt.rn.bf16x2.f32 %0, %1, %2;" : "=r"(r) : "f"(hi), "f"(lo)); return r;
}
template<int OFF>
__device__ __forceinline__ unsigned lds32o(unsigned addr) {
    unsigned v; asm("ld.shared.b32 %0, [%1+%2];" : "=r"(v) : "r"(addr), "n"(OFF)); return v;
}
__device__ __forceinline__ void mma_bf16(
    float& d0, float& d1, float& d2, float& d3,
    unsigned a0, unsigned a1, unsigned b0,
    float c0, float c1, float c2, float c3)
{
    asm("mma.sync.aligned.m16n8k8.row.col.f32.bf16.bf16.f32 "
        "{%0,%1,%2,%3},{%4,%5},{%6},{%7,%8,%9,%10};"
        : "=f"(d0), "=f"(d1), "=f"(d2), "=f"(d3)
        : "r"(a0), "r"(a1), "r"(b0), "f"(c0), "f"(c1), "f"(c2), "f"(c3));
}

// ---------------------------------------------------------------------------
// Kernel 0: parallel weight folding (24 blocks) + bias/mask-detect (block 24).
// Q-groups (0,3) absorb ATT_SCALE*log2(e) -> scores land in exp2 domain.
// ---------------------------------------------------------------------------
__global__ void k_setup(const float* __restrict__ wp, const float* __restrict__ bp,
                        WPtrs P, const void* __restrict__ m) {
    int tid = threadIdx.x;
    int blk = blockIdx.x;
    if (blk < 24) {
        int idx = blk*512 + tid;      // two outputs per thread
        #pragma unroll
        for (int rep = 0; rep < 2; rep++, idx += 256) {
            int g = idx / 2048;
            int r = idx & 2047;
            int i = r >> 5, o = r & 31;
            const float* wx = P.w[g];
            float acc = 0.f;
            #pragma unroll
            for (int c = 0; c < 32; c++) acc += wx[o*32 + c] * wp[c*64 + i];
            if (g == 0 || g == 3) acc *= ATT_SCALE * LOG2E;
            d_wc[idx] = acc;
        }
    } else {
        if (tid < 192) {
            int g = tid >> 5, o = tid & 31;
            const float* wx = P.w[g];
            float acc = P.b[g][o];
            for (int c = 0; c < 32; c++) acc += wx[o*32 + c] * bp[c];
            if (g == 0 || g == 3) acc *= ATT_SCALE * LOG2E;
            d_bc[tid] = acc;
        }
        __shared__ int oki, okf;
        if (tid == 0) { oki = 1; okf = 1; }
        __syncthreads();
        const unsigned int* p = (const unsigned int*)m;
        for (int idx = tid; idx < 4096; idx += 256) {
            unsigned int v = p[idx];
            if (v != 0u && v != 1u) oki = 0;
            float f = __uint_as_float(v);
            if (f != 0.0f && f != 1.0f) okf = 0;
        }
        __syncthreads();
        if (tid == 0) d_mask_mode = oki ? 0 : (okf ? 1 : 2);
    }
}

// ---------------------------------------------------------------------------
// Mask bit-pack to per-row words: d_maskw[n][w], bit j = mask[n][w*32+j].
// ---------------------------------------------------------------------------
__global__ void k_maskpack(const void* __restrict__ m) {
    int n = blockIdx.x;
    int j = threadIdx.x;
    int mode = d_mask_mode;
    bool v;
    if (mode == 0)      v = ((const int*)m)[n*NN + j] != 0;
    else if (mode == 1) v = ((const float*)m)[n*NN + j] != 0.0f;
    else                v = ((const unsigned char*)m)[n*NN + j] != 0;
    unsigned int word = __ballot_sync(0xffffffffu, v);
    if ((j & 31) == 0) d_maskw[n*16 + (j >> 5)] = word;
}

// ---------------------------------------------------------------------------
// Kernel 1: QKV from x, emitting bf16 in MMA-friendly layouts.
//   q/k (g 0,1,3,4) -> d_qt[qi][bt][h][n][8]   (transposed per head)
//   v   (g 2,5)     -> d_vt[vi][bt][h][8][n]   (native per head)
// ---------------------------------------------------------------------------
__global__ __launch_bounds__(256) void k_qkv(const float* __restrict__ x) {
    __shared__ float xs[64*128];   // [ci][n]
    __shared__ float ws[64*32];    // [ci][o]
    int bt = blockIdx.x;
    int ntile = blockIdx.y;
    int b = bt / NT, t = bt % NT;
    int tid = threadIdx.x;

    for (int idx = tid; idx < 64*128; idx += 256) {
        int ci = idx >> 7, n = idx & 127;
        xs[idx] = x[((b*64 + ci)*NT + t)*NN + ntile*128 + n];
    }

    int nt = tid & 31, grp = tid >> 5;
    int n0 = nt*4, o0 = grp*4;
    int h = o0 >> 3;

    for (int g = 0; g < 6; g++) {
        __syncthreads();
        for (int idx = tid; idx < 2048; idx += 256) ws[idx] = d_wc[g*2048 + idx];
        __syncthreads();

        float acc[4][4];
        #pragma unroll
        for (int i = 0; i < 4; i++) {
            float bias = d_bc[g*32 + o0 + i];
            #pragma unroll
            for (int j = 0; j < 4; j++) acc[i][j] = bias;
        }
        #pragma unroll 4
        for (int ci = 0; ci < 64; ci++) {
            float4 xv = *(const float4*)&xs[ci*128 + n0];
            float4 wv = *(const float4*)&ws[ci*32 + o0];
            float xa[4] = {xv.x, xv.y, xv.z, xv.w};
            float wa[4] = {wv.x, wv.y, wv.z, wv.w};
            #pragma unroll
            for (int i = 0; i < 4; i++)
                #pragma unroll
                for (int j = 0; j < 4; j++) acc[i][j] += wa[i]*xa[j];
        }

        if (g == 2 || g == 5) {
            int vi = (g == 5) ? 1 : 0;
            int dd = o0 & 7;
            #pragma unroll
            for (int i = 0; i < 4; i++) {
                unsigned lo = bf2(acc[i][0], acc[i][1]);
                unsigned hi = bf2(acc[i][2], acc[i][3]);
                long long base = ((((long long)vi*NBT + bt)*4 + h)*8 + dd + i)*NN
                                 + ntile*128 + n0;
                *(uint2*)((__nv_bfloat16*)d_vt + base) = make_uint2(lo, hi);
            }
        } else {
            int qi = (g < 2) ? g : g - 1;   // 0->0,1->1,3->2,4->3
            int d0 = o0 & 7;
            #pragma unroll
            for (int j = 0; j < 4; j++) {
                unsigned lo = bf2(acc[0][j], acc[1][j]);
                unsigned hi = bf2(acc[2][j], acc[3][j]);
                int n = ntile*128 + n0 + j;
                long long base = ((((long long)qi*NBT + bt)*4 + h)*NN + n)*8 + d0;
                *(uint2*)((__nv_bfloat16*)d_qt + base) = make_uint2(lo, hi);
            }
        }
    }
}

// ---------------------------------------------------------------------------
// Kernel 2: flash attention via mma.sync m16n8k8 bf16.
// Fully-unrolled key loop (immediate-offset LDS), mask rows preloaded as
// uint4 pairs, softmax denominator via ones-MMA (no FADDs, no shuffles).
// ---------------------------------------------------------------------------
#define VSTRIDE 1040   // bytes; 1040/4 = 260 ≡ 4 (mod 32) -> banks (4g+tq) all distinct

template<bool MASKED>
__device__ __forceinline__ void attn_mma(
    unsigned ksb, unsigned vsb,
    const unsigned* __restrict__ qgu,
    float* __restrict__ outp)
{
    int tid = threadIdx.x, lane = tid & 31, wid = tid >> 5;
    int g = lane >> 2, tq = lane & 3;
    unsigned kbase = ksb + g*16 + tq*4;
    unsigned vbase = vsb + g*VSTRIDE + tq*4;
    int sh0 = tq*2;

    for (int tile = wid; tile < 32; tile += 4) {
        int qbase = tile * 16;
        int r0 = qbase + g, r1 = r0 + 8;
        unsigned qa0 = __ldg(qgu + r0*4 + tq);
        unsigned qa1 = __ldg(qgu + r1*4 + tq);

        unsigned mr0[16], mr1[16];
        if (MASKED) {
            *(uint4*)&mr0[0]  = __ldg((const uint4*)&d_maskw[r0*16]);
            *(uint4*)&mr0[4]  = __ldg((const uint4*)&d_maskw[r0*16 + 4]);
            *(uint4*)&mr0[8]  = __ldg((const uint4*)&d_maskw[r0*16 + 8]);
            *(uint4*)&mr0[12] = __ldg((const uint4*)&d_maskw[r0*16 + 12]);
            *(uint4*)&mr1[0]  = __ldg((const uint4*)&d_maskw[r1*16]);
            *(uint4*)&mr1[4]  = __ldg((const uint4*)&d_maskw[r1*16 + 4]);
            *(uint4*)&mr1[8]  = __ldg((const uint4*)&d_maskw[r1*16 + 8]);
            *(uint4*)&mr1[12] = __ldg((const uint4*)&d_maskw[r1*16 + 12]);
        }

        float o0 = 0.f, o1 = 0.f, o2 = 0.f, o3 = 0.f;
        float L0 = 0.f, L1 = 0.f, L2 = 0.f, L3 = 0.f;

        #pragma unroll
        for (int cw = 0; cw < 16; cw++) {
            #pragma unroll
            for (int sub = 0; sub < 4; sub++) {
                const int j = cw*4 + sub;
                unsigned kb = lds32o<0>(kbase + j*128);
                float s0, s1, s2, s3;
                mma_bf16(s0, s1, s2, s3, qa0, qa1, kb, 0.f, 0.f, 0.f, 0.f);
                if (MASKED) {
                    unsigned b0 = mr0[cw] >> (sub*8 + sh0);
                    unsigned b1 = mr1[cw] >> (sub*8 + sh0);
                    if (b0 & 1u) s0 = NINF;
                    if (b0 & 2u) s1 = NINF;
                    if (b1 & 1u) s2 = NINF;
                    if (b1 & 2u) s3 = NINF;
                }
                float p0 = ex2f(s0), p1 = ex2f(s1), p2 = ex2f(s2), p3 = ex2f(s3);
                unsigned pa0 = bf2(p0, p1);
                unsigned pa1 = bf2(p2, p3);
                // denominator: P x ones -> every lane's L0 = rowsum(r0), L2 = rowsum(r1)
                mma_bf16(L0, L1, L2, L3, pa0, pa1, ONESBF, L0, L1, L2, L3);
                unsigned vb = lds32o<0>(vbase + j*16);
                mma_bf16(o0, o1, o2, o3, pa0, pa1, vb, o0, o1, o2, o3);
            }
        }
        float inv0 = rcpf(L0), inv1 = rcpf(L2);
        *(float2*)&outp[r0*8 + 2*tq] = make_float2(o0*inv0, o1*inv0);
        *(float2*)&outp[r1*8 + 2*tq] = make_float2(o2*inv1, o3*inv1);
    }
}

__global__ __launch_bounds__(128) void k_attn4() {
    __shared__ __align__(16) unsigned char ksm[NN*16];       // K [n][8] bf16, 8KB
    __shared__ __align__(16) unsigned char vsm[8*VSTRIDE];   // V [d][n] bf16, padded
    int bt = blockIdx.x, h = blockIdx.y, blk = blockIdx.z;
    int tid = threadIdx.x;

    int qi = blk ? 2 : 0;   // blk0(geo)->slot 0, blk1(plain)->slot 2
    int ki = blk ? 3 : 1;
    int vi = blk ? 1 : 0;

    const __nv_bfloat16* qg = d_qt + ((((long long)qi*NBT + bt)*4 + h)*NN)*8;
    const __nv_bfloat16* kg = d_qt + ((((long long)ki*NBT + bt)*4 + h)*NN)*8;
    const __nv_bfloat16* vg = d_vt + ((((long long)vi*NBT + bt)*4 + h)*8)*NN;

    {
        const uint4* kg4 = (const uint4*)kg;
        const uint4* vg4 = (const uint4*)vg;
        uint4* ks4 = (uint4*)ksm;
        for (int i = tid; i < 512; i += 128) {
            ks4[i] = kg4[i];
            uint4 v = vg4[i];
            int r = i >> 6, c = i & 63;
            *(uint4*)(vsm + r*VSTRIDE + c*16) = v;
        }
    }
    __syncthreads();

    unsigned ksb = (unsigned)__cvta_generic_to_shared(ksm);
    unsigned vsb = (unsigned)__cvta_generic_to_shared(vsm);
    int b = bt / NT, t = bt % NT;
    float* outp = d_attn + (blk*NB + b)*(4*NT*NN*8) + (h*NT + t)*(NN*8);

    if (blk == 0) attn_mma<true >(ksb, vsb, (const unsigned*)qg, outp);
    else          attn_mma<false>(ksb, vsb, (const unsigned*)qg, outp);
}

// ---------------------------------------------------------------------------
// Kernel 3: coalesced torch-faithful gather + residual + ReLU via smem
// transpose. Per CTA: (bt, sel, 128-row n-tile). Reads 128B rows, writes
// coalesced channel rows; smem padded to 33 -> conflict-free column reads.
// ---------------------------------------------------------------------------
__global__ __launch_bounds__(256) void k_final(const float* __restrict__ x,
                                               float* __restrict__ out) {
    __shared__ float sm[128*33];
    int bt = blockIdx.x, sel = blockIdx.y, ntile = blockIdx.z;
    int tid = threadIdx.x;
    int b = bt / NT, t = bt % NT;
    int n0 = ntile * 128;
    int blk = 1 - sel;              // sel0 -> plain(blk1) c0..31, sel1 -> geo(blk0) c32..63
    int cbase = sel * 32;

    const float* ab = d_attn + (blk*NB + b)*(4*NT*NN*8);
    for (int idx = tid; idx < 128*32; idx += 256) {
        int r = idx >> 5, cc = idx & 31;
        sm[r*33 + cc] = ab[(n0 + r)*384 + t*32 + cc];   // 128B coalesced per warp
    }
    __syncthreads();

    int nl = tid & 127, chalf = tid >> 7;
    #pragma unroll
    for (int k = 0; k < 16; k++) {
        int cl = k*2 + chalf;
        int c = cbase + cl;
        long long xi = ((long long)(b*64 + c)*NT + t)*NN + n0 + nl;
        out[xi] = fmaxf(sm[nl*33 + cl] + x[xi], 0.f);
    }
}

// ---------------------------------------------------------------------------
extern "C" void kernel_launch(void* const* d_in, const int* in_sizes, int n_in,
                              void* d_out, int out_size) {
    const float* x    = (const float*)d_in[0];
    const void*  mask = d_in[1];
    const float* wp   = (const float*)d_in[2];
    const float* bp   = (const float*)d_in[3];
    WPtrs P;
    for (int g = 0; g < 6; g++) {
        P.w[g] = (const float*)d_in[4 + 2*g];
        P.b[g] = (const float*)d_in[5 + 2*g];
    }

    k_setup   <<<25, 256>>>(wp, bp, P, mask);
    k_maskpack<<<NN, NN>>>(mask);
    k_qkv     <<<dim3(NBT, 4), 256>>>(x);
    k_attn4   <<<dim3(NBT, 4, 2), 128>>>();
    k_final   <<<dim3(NBT, 2, 4), 256>>>(x, (float*)d_out);
}

// round 12
// speedup vs baseline: 5.3703x; 1.1629x over previous
#include <cuda_runtime.h>
#include <cuda_bf16.h>
#include <math.h>
#include <stdint.h>

// Problem dims
#define NB 8
#define NT 12
#define NN 512
#define NBT 96
#define ATT_SCALE 0.35355339059327373f   // 8^-0.5
#define LOG2E 1.4426950408889634f
#define ONESBF 0x3F803F80u               // bf16 1.0 x2

// Scratch (static __device__ — no allocations allowed)
__device__ float d_bc[6*32];                    // combined biases [row = g*32+o]
__device__ __nv_bfloat16 d_wcb[192*64];         // combined weights bf16 [row][ci]
__device__ __nv_bfloat16 d_qt[4*NBT*4*NN*8];    // [qi][bt][h][n][d]  (q/k)
__device__ __nv_bfloat16 d_vt[2*NBT*4*8*NN];    // [vi][bt][h][d][n]  (v)
__device__ float d_attn[2*NB*4*NT*NN*8];        // [blk][b][h][t][n][d] flat
__device__ unsigned d_ms[NN*NN/2];              // bf16 AND-mask [row][key/2]
__device__ int d_mask_mode;

struct WPtrs { const float* w[6]; const float* b[6]; };

// ---------------- helpers ----------------
__device__ __forceinline__ float ex2f(float x) {
    float r; asm("ex2.approx.f32 %0, %1;" : "=f"(r) : "f"(x)); return r;
}
__device__ __forceinline__ float rcpf(float x) {
    float r; asm("rcp.approx.f32 %0, %1;" : "=f"(r) : "f"(x)); return r;
}
__device__ __forceinline__ unsigned bf2(float lo, float hi) {
    unsigned r; asm("cvt.rn.bf16x2.f32 %0, %1, %2;" : "=r"(r) : "f"(hi), "f"(lo)); return r;
}
template<int OFF>
__device__ __forceinline__ unsigned lds32o(unsigned addr) {
    unsigned v; asm("ld.shared.b32 %0, [%1+%2];" : "=r"(v) : "r"(addr), "n"(OFF)); return v;
}
__device__ __forceinline__ void mma_bf16(
    float& d0, float& d1, float& d2, float& d3,
    unsigned a0, unsigned a1, unsigned b0,
    float c0, float c1, float c2, float c3)
{
    asm("mma.sync.aligned.m16n8k8.row.col.f32.bf16.bf16.f32 "
        "{%0,%1,%2,%3},{%4,%5},{%6},{%7,%8,%9,%10};"
        : "=f"(d0), "=f"(d1), "=f"(d2), "=f"(d3)
        : "r"(a0), "r"(a1), "r"(b0), "f"(c0), "f"(c1), "f"(c2), "f"(c3));
}
__device__ __forceinline__ void mma16816(
    float& d0, float& d1, float& d2, float& d3,
    unsigned a0, unsigned a1, unsigned a2, unsigned a3,
    unsigned b0, unsigned b1,
    float c0, float c1, float c2, float c3)
{
    asm("mma.sync.aligned.m16n8k16.row.col.f32.bf16.bf16.f32 "
        "{%0,%1,%2,%3},{%4,%5,%6,%7},{%8,%9},{%10,%11,%12,%13};"
        : "=f"(d0), "=f"(d1), "=f"(d2), "=f"(d3)
        : "r"(a0), "r"(a1), "r"(a2), "r"(a3), "r"(b0), "r"(b1),
          "f"(c0), "f"(c1), "f"(c2), "f"(c3));
}

// ---------------------------------------------------------------------------
// Kernel 0: blocks 0-23 = weight folding -> bf16 [row][ci]; block 24 = bias +
// mask dtype detect. Q-groups (0,3) absorb ATT_SCALE*log2(e).
// ---------------------------------------------------------------------------
__global__ void k_setup(const float* __restrict__ wp, const float* __restrict__ bp,
                        WPtrs P, const void* __restrict__ m) {
    int tid = threadIdx.x;
    int blk = blockIdx.x;
    if (blk < 24) {
        int idx = blk*512 + tid;
        #pragma unroll
        for (int rep = 0; rep < 2; rep++, idx += 256) {
            int g = idx / 2048;
            int r = idx & 2047;
            int i = r >> 5, o = r & 31;
            const float* wx = P.w[g];
            float acc = 0.f;
            #pragma unroll
            for (int c = 0; c < 32; c++) acc += wx[o*32 + c] * wp[c*64 + i];
            if (g == 0 || g == 3) acc *= ATT_SCALE * LOG2E;
            d_wcb[(g*32 + o)*64 + i] = __float2bfloat16(acc);
        }
    } else {
        if (tid < 192) {
            int g = tid >> 5, o = tid & 31;
            const float* wx = P.w[g];
            float acc = P.b[g][o];
            for (int c = 0; c < 32; c++) acc += wx[o*32 + c] * bp[c];
            if (g == 0 || g == 3) acc *= ATT_SCALE * LOG2E;
            d_bc[tid] = acc;
        }
        __shared__ int oki, okf;
        if (tid == 0) { oki = 1; okf = 1; }
        __syncthreads();
        const unsigned int* p = (const unsigned int*)m;
        for (int idx = tid; idx < 4096; idx += 256) {
            unsigned int v = p[idx];
            if (v != 0u && v != 1u) oki = 0;
            float f = __uint_as_float(v);
            if (f != 0.0f && f != 1.0f) okf = 0;
        }
        __syncthreads();
        if (tid == 0) d_mask_mode = oki ? 0 : (okf ? 1 : 2);
    }
}

// ---------------------------------------------------------------------------
// Mask -> bf16 AND table: d_ms halves, 0xFFFF keep / 0x0000 masked.
// ---------------------------------------------------------------------------
__global__ void k_maskpack(const void* __restrict__ m) {
    int n = blockIdx.x;
    int j = threadIdx.x;
    int mode = d_mask_mode;
    bool v;
    if (mode == 0)      v = ((const int*)m)[n*NN + j] != 0;
    else if (mode == 1) v = ((const float*)m)[n*NN + j] != 0.0f;
    else                v = ((const unsigned char*)m)[n*NN + j] != 0;
    ((unsigned short*)d_ms)[n*NN + j] = v ? 0 : 0xFFFFu;
}

// ---------------------------------------------------------------------------
// Kernel 1: QKV as bf16 MMA GEMM. C[192 x 128n] = W[192x64] * X[64 x 128n]
// per (bt, n-quarter). X converted f32->bf16 into smem [n][ci] (stride 36
// words -> B-frag banks 4g+tq, conflict-free). f32 accum, bias in C-init.
// ---------------------------------------------------------------------------
__global__ __launch_bounds__(256) void k_qkv2(const float* __restrict__ x) {
    __shared__ unsigned xs[128*36];   // [n_local][ci-pair], padded stride 36
    int bt = blockIdx.x, nq = blockIdx.y;
    int b = bt / NT, t = bt % NT;
    int tid = threadIdx.x;

    const float* xg = x + (long long)b*64*6144 + t*512 + nq*128;
    #pragma unroll 4
    for (int it = 0; it < 16; it++) {
        int idx = it*256 + tid;
        int cp = idx >> 7, nl = idx & 127;
        float f0 = __ldg(xg + (2*cp)*6144 + nl);
        float f1 = __ldg(xg + (2*cp+1)*6144 + nl);
        xs[nl*36 + cp] = bf2(f0, f1);
    }
    __syncthreads();

    int lane = tid & 31, w = tid >> 5;
    int g = lane >> 2, tq = lane & 3;
    int mset0 = w & 3;            // mtiles mset0, +4, +8
    int nrb = (w >> 2) * 8;       // 8 n-tiles per warp

    // A-frags + biases (registers, reused across all n-tiles)
    unsigned A[3][4][4];
    float bia[3][2];
    #pragma unroll
    for (int mi = 0; mi < 3; mi++) {
        int mt = mset0 + mi*4;
        int R0 = mt*16 + g, R1 = R0 + 8;
        bia[mi][0] = d_bc[R0]; bia[mi][1] = d_bc[R1];
        const unsigned* w0 = (const unsigned*)(d_wcb + R0*64);
        const unsigned* w1 = (const unsigned*)(d_wcb + R1*64);
        #pragma unroll
        for (int ks = 0; ks < 4; ks++) {
            A[mi][ks][0] = __ldg(w0 + ks*8 + tq);
            A[mi][ks][1] = __ldg(w1 + ks*8 + tq);
            A[mi][ks][2] = __ldg(w0 + ks*8 + 4 + tq);
            A[mi][ks][3] = __ldg(w1 + ks*8 + 4 + tq);
        }
    }

    for (int nt0 = 0; nt0 < 8; nt0++) {
        int ntile = nrb + nt0;
        const unsigned* xr = xs + (ntile*8 + g)*36;
        unsigned B[4][2];
        #pragma unroll
        for (int ks = 0; ks < 4; ks++) { B[ks][0] = xr[ks*8 + tq]; B[ks][1] = xr[ks*8 + 4 + tq]; }

        #pragma unroll
        for (int mi = 0; mi < 3; mi++) {
            float c0 = bia[mi][0], c1 = bia[mi][0], c2 = bia[mi][1], c3 = bia[mi][1];
            #pragma unroll
            for (int ks = 0; ks < 4; ks++)
                mma16816(c0,c1,c2,c3, A[mi][ks][0],A[mi][ks][1],A[mi][ks][2],A[mi][ks][3],
                         B[ks][0], B[ks][1], c0,c1,c2,c3);

            int mt = mset0 + mi*4;
            int R0 = mt*16 + g;
            int g6 = mt >> 1;
            int o0 = R0 & 31, h0 = o0 >> 3, d0 = o0 & 7;   // R1 -> h0+1, same d0
            int n = nq*128 + ntile*8 + 2*tq;
            if (g6 == 2 || g6 == 5) {
                int vi = (g6 == 5);
                __nv_bfloat16* vt0 = d_vt + ((((vi*NBT + bt)*4 + h0    )*8 + d0)*NN);
                __nv_bfloat16* vt1 = d_vt + ((((vi*NBT + bt)*4 + h0 + 1)*8 + d0)*NN);
                *(unsigned*)(vt0 + n) = bf2(c0, c1);
                *(unsigned*)(vt1 + n) = bf2(c2, c3);
            } else {
                int qi = (g6 < 2) ? g6 : g6 - 1;   // 0,1,3,4 -> 0,1,2,3
                __nv_bfloat16* q0 = d_qt + (((qi*NBT + bt)*4 + h0    )*NN)*8;
                __nv_bfloat16* q1 = d_qt + (((qi*NBT + bt)*4 + h0 + 1)*NN)*8;
                q0[n*8 + d0]     = __float2bfloat16(c0);
                q0[(n+1)*8 + d0] = __float2bfloat16(c1);
                q1[n*8 + d0]     = __float2bfloat16(c2);
                q1[(n+1)*8 + d0] = __float2bfloat16(c3);
            }
        }
    }
}

// ---------------------------------------------------------------------------
// Kernel 2: flash attention. QK via m16n8k8; P/V and denominator via
// m16n8k16 (4 P-frags = A). Mask = AND with L2-resident bf16 table.
// ---------------------------------------------------------------------------
#define VSTRIDE 1040   // 1040/4 = 260 ≡ 4 (mod 32) -> banks 4g+tq distinct

template<bool MASKED>
__device__ __forceinline__ void attn_loop5(
    unsigned ksb, unsigned vsb,
    const unsigned* __restrict__ qgu,
    float* __restrict__ outp)
{
    int tid = threadIdx.x, lane = tid & 31, wid = tid >> 5;
    int g = lane >> 2, tq = lane & 3;
    unsigned kbase = ksb + g*16 + tq*4;
    unsigned vbase = vsb + g*VSTRIDE + tq*4;

    for (int tile = wid; tile < 32; tile += 4) {
        int r0 = tile*16 + g, r1 = r0 + 8;
        unsigned qa0 = __ldg(qgu + r0*4 + tq);
        unsigned qa1 = __ldg(qgu + r1*4 + tq);
        const unsigned* mb0 = d_ms + r0*256 + tq;
        const unsigned* mb1 = d_ms + r1*256 + tq;

        float o0=0.f,o1=0.f,o2=0.f,o3=0.f;
        float L0=0.f,L1=0.f,L2=0.f,L3=0.f;

        #pragma unroll
        for (int cw = 0; cw < 16; cw++) {
            unsigned m[8];
            if (MASKED) {
                #pragma unroll
                for (int s = 0; s < 4; s++) {
                    m[2*s]   = __ldg(mb0 + cw*16 + s*4);
                    m[2*s+1] = __ldg(mb1 + cw*16 + s*4);
                }
            }
            unsigned pa[8];
            #pragma unroll
            for (int s = 0; s < 4; s++) {
                unsigned kb = lds32o<0>(kbase + (cw*4 + s)*128);
                float s0,s1,s2,s3;
                mma_bf16(s0,s1,s2,s3, qa0,qa1, kb, 0.f,0.f,0.f,0.f);
                float p0 = ex2f(s0), p1 = ex2f(s1), p2 = ex2f(s2), p3 = ex2f(s3);
                unsigned x0 = bf2(p0,p1), x1 = bf2(p2,p3);
                if (MASKED) { x0 &= m[2*s]; x1 &= m[2*s+1]; }
                pa[2*s] = x0; pa[2*s+1] = x1;
            }
            #pragma unroll
            for (int hf = 0; hf < 2; hf++) {
                unsigned a0 = pa[hf*4+0], a1 = pa[hf*4+1], a2 = pa[hf*4+2], a3 = pa[hf*4+3];
                mma16816(L0,L1,L2,L3, a0,a1,a2,a3, ONESBF,ONESBF, L0,L1,L2,L3);
                unsigned vb0 = lds32o<0> (vbase + cw*64 + hf*32);
                unsigned vb1 = lds32o<16>(vbase + cw*64 + hf*32);
                mma16816(o0,o1,o2,o3, a0,a1,a2,a3, vb0,vb1, o0,o1,o2,o3);
            }
        }
        float inv0 = rcpf(L0), inv1 = rcpf(L2);
        *(float2*)&outp[r0*8 + 2*tq] = make_float2(o0*inv0, o1*inv0);
        *(float2*)&outp[r1*8 + 2*tq] = make_float2(o2*inv1, o3*inv1);
    }
}

__global__ __launch_bounds__(128) void k_attn5() {
    __shared__ __align__(16) unsigned char ksm[NN*16];       // K [n][8] bf16
    __shared__ __align__(16) unsigned char vsm[8*VSTRIDE];   // V [d][n] bf16, padded
    int bt = blockIdx.x, h = blockIdx.y, blk = blockIdx.z;
    int tid = threadIdx.x;

    int qi = blk ? 2 : 0;
    int ki = blk ? 3 : 1;
    int vi = blk ? 1 : 0;

    const __nv_bfloat16* qg = d_qt + ((((long long)qi*NBT + bt)*4 + h)*NN)*8;
    const __nv_bfloat16* kg = d_qt + ((((long long)ki*NBT + bt)*4 + h)*NN)*8;
    const __nv_bfloat16* vg = d_vt + ((((long long)vi*NBT + bt)*4 + h)*8)*NN;

    {
        const uint4* kg4 = (const uint4*)kg;
        const uint4* vg4 = (const uint4*)vg;
        uint4* ks4 = (uint4*)ksm;
        for (int i = tid; i < 512; i += 128) {
            ks4[i] = kg4[i];
            uint4 v = vg4[i];
            int r = i >> 6, c = i & 63;
            *(uint4*)(vsm + r*VSTRIDE + c*16) = v;
        }
    }
    __syncthreads();

    unsigned ksb = (unsigned)__cvta_generic_to_shared(ksm);
    unsigned vsb = (unsigned)__cvta_generic_to_shared(vsm);
    int b = bt / NT, t = bt % NT;
    float* outp = d_attn + (blk*NB + b)*(4*NT*NN*8) + (h*NT + t)*(NN*8);

    if (blk == 0) attn_loop5<true >(ksb, vsb, (const unsigned*)qg, outp);
    else          attn_loop5<false>(ksb, vsb, (const unsigned*)qg, outp);
}

// ---------------------------------------------------------------------------
// Kernel 3: coalesced torch-faithful gather + residual + ReLU (R8-proven).
// ---------------------------------------------------------------------------
__global__ __launch_bounds__(256) void k_final(const float* __restrict__ x,
                                               float* __restrict__ out) {
    __shared__ float sm[128*33];
    int bt = blockIdx.x, sel = blockIdx.y, ntile = blockIdx.z;
    int tid = threadIdx.x;
    int b = bt / NT, t = bt % NT;
    int n0 = ntile * 128;
    int blk = 1 - sel;
    int cbase = sel * 32;

    const float* ab = d_attn + (blk*NB + b)*(4*NT*NN*8);
    for (int idx = tid; idx < 128*32; idx += 256) {
        int r = idx >> 5, cc = idx & 31;
        sm[r*33 + cc] = ab[(n0 + r)*384 + t*32 + cc];
    }
    __syncthreads();

    int nl = tid & 127, chalf = tid >> 7;
    #pragma unroll
    for (int k = 0; k < 16; k++) {
        int cl = k*2 + chalf;
        int c = cbase + cl;
        long long xi = ((long long)(b*64 + c)*NT + t)*NN + n0 + nl;
        out[xi] = fmaxf(sm[nl*33 + cl] + x[xi], 0.f);
    }
}

// ---------------------------------------------------------------------------
extern "C" void kernel_launch(void* const* d_in, const int* in_sizes, int n_in,
                              void* d_out, int out_size) {
    const float* x    = (const float*)d_in[0];
    const void*  mask = d_in[1];
    const float* wp   = (const float*)d_in[2];
    const float* bp   = (const float*)d_in[3];
    WPtrs P;
    for (int g = 0; g < 6; g++) {
        P.w[g] = (const float*)d_in[4 + 2*g];
        P.b[g] = (const float*)d_in[5 + 2*g];
    }

    k_setup   <<<25, 256>>>(wp, bp, P, mask);
    k_maskpack<<<NN, NN>>>(mask);
    k_qkv2    <<<dim3(NBT, 4), 256>>>(x);
    k_attn5   <<<dim3(NBT, 4, 2), 128>>>();
    k_final   <<<dim3(NBT, 2, 4), 256>>>(x, (float*)d_out);
}

// round 16
// speedup vs baseline: 8.0690x; 1.5025x over previous
#include <cuda_runtime.h>
#include <cuda_bf16.h>
#include <math.h>
#include <stdint.h>

// Problem dims
#define NB 8
#define NT 12
#define NN 512
#define NBT 96
#define ATT_SCALE 0.35355339059327373f   // 8^-0.5
#define LOG2E 1.4426950408889634f
#define ONESH 0x3C003C00u                // f16 1.0 x2

// Scratch (static __device__ — no allocations allowed)
__device__ float d_bc[6*32];                    // combined biases [row = g*32+o]
__device__ __nv_bfloat16 d_wcb[192*64];         // combined weights bf16 [row][ci]
__device__ __nv_bfloat16 d_qt[4*NBT*4*NN*8];    // [qi][bt][h][n][d]  (q/k, bf16)
__device__ unsigned short d_vt[2*NBT*4*8*NN];   // [vi][bt][h][d][n]  (v, f16 bits)
__device__ float d_attn[2*NB*4*NT*NN*8];        // [blk][b][h][t][n][d] flat
__device__ unsigned d_ms[NN*NN/2];              // f16 AND-mask [row][key-pair]
__device__ uint2 d_msp[32*16*4*32];             // permuted: [tile][cw][s][lane] -> (r0,r1)
__device__ int d_mask_mode;

struct WPtrs { const float* w[6]; const float* b[6]; };

// ---------------- helpers ----------------
__device__ __forceinline__ float rcpf(float x) {
    float r; asm("rcp.approx.f32 %0, %1;" : "=f"(r) : "f"(x)); return r;
}
__device__ __forceinline__ unsigned bf2(float lo, float hi) {
    unsigned r; asm("cvt.rn.bf16x2.f32 %0, %1, %2;" : "=r"(r) : "f"(hi), "f"(lo)); return r;
}
__device__ __forceinline__ unsigned h2p(float lo, float hi) {
    unsigned r; asm("cvt.rn.f16x2.f32 %0, %1, %2;" : "=r"(r) : "f"(hi), "f"(lo)); return r;
}
__device__ __forceinline__ unsigned ex2h2(unsigned x) {
    unsigned r; asm("ex2.approx.f16x2 %0, %1;" : "=r"(r) : "r"(x)); return r;
}
template<int OFF>
__device__ __forceinline__ unsigned lds32o(unsigned addr) {
    unsigned v; asm("ld.shared.b32 %0, [%1+%2];" : "=r"(v) : "r"(addr), "n"(OFF)); return v;
}
__device__ __forceinline__ void mma_bf16(
    float& d0, float& d1, float& d2, float& d3,
    unsigned a0, unsigned a1, unsigned b0,
    float c0, float c1, float c2, float c3)
{
    asm("mma.sync.aligned.m16n8k8.row.col.f32.bf16.bf16.f32 "
        "{%0,%1,%2,%3},{%4,%5},{%6},{%7,%8,%9,%10};"
        : "=f"(d0), "=f"(d1), "=f"(d2), "=f"(d3)
        : "r"(a0), "r"(a1), "r"(b0), "f"(c0), "f"(c1), "f"(c2), "f"(c3));
}
__device__ __forceinline__ void mma16816(
    float& d0, float& d1, float& d2, float& d3,
    unsigned a0, unsigned a1, unsigned a2, unsigned a3,
    unsigned b0, unsigned b1,
    float c0, float c1, float c2, float c3)
{
    asm("mma.sync.aligned.m16n8k16.row.col.f32.bf16.bf16.f32 "
        "{%0,%1,%2,%3},{%4,%5,%6,%7},{%8,%9},{%10,%11,%12,%13};"
        : "=f"(d0), "=f"(d1), "=f"(d2), "=f"(d3)
        : "r"(a0), "r"(a1), "r"(a2), "r"(a3), "r"(b0), "r"(b1),
          "f"(c0), "f"(c1), "f"(c2), "f"(c3));
}
__device__ __forceinline__ void mma16816h(
    float& d0, float& d1, float& d2, float& d3,
    unsigned a0, unsigned a1, unsigned a2, unsigned a3,
    unsigned b0, unsigned b1,
    float c0, float c1, float c2, float c3)
{
    asm("mma.sync.aligned.m16n8k16.row.col.f32.f16.f16.f32 "
        "{%0,%1,%2,%3},{%4,%5,%6,%7},{%8,%9},{%10,%11,%12,%13};"
        : "=f"(d0), "=f"(d1), "=f"(d2), "=f"(d3)
        : "r"(a0), "r"(a1), "r"(a2), "r"(a3), "r"(b0), "r"(b1),
          "f"(c0), "f"(c1), "f"(c2), "f"(c3));
}

// ---------------------------------------------------------------------------
// Kernel 0: blocks 0-23 = weight folding -> bf16 [row][ci]; block 24 = bias +
// mask dtype detect. Q-groups (0,3) absorb ATT_SCALE*log2(e).
// ---------------------------------------------------------------------------
__global__ void k_setup(const float* __restrict__ wp, const float* __restrict__ bp,
                        WPtrs P, const void* __restrict__ m) {
    int tid = threadIdx.x;
    int blk = blockIdx.x;
    if (blk < 24) {
        int idx = blk*512 + tid;
        #pragma unroll
        for (int rep = 0; rep < 2; rep++, idx += 256) {
            int g = idx / 2048;
            int r = idx & 2047;
            int i = r >> 5, o = r & 31;
            const float* wx = P.w[g];
            float acc = 0.f;
            #pragma unroll
            for (int c = 0; c < 32; c++) acc += wx[o*32 + c] * wp[c*64 + i];
            if (g == 0 || g == 3) acc *= ATT_SCALE * LOG2E;
            d_wcb[(g*32 + o)*64 + i] = __float2bfloat16(acc);
        }
    } else {
        if (tid < 192) {
            int g = tid >> 5, o = tid & 31;
            const float* wx = P.w[g];
            float acc = P.b[g][o];
            for (int c = 0; c < 32; c++) acc += wx[o*32 + c] * bp[c];
            if (g == 0 || g == 3) acc *= ATT_SCALE * LOG2E;
            d_bc[tid] = acc;
        }
        __shared__ int oki, okf;
        if (tid == 0) { oki = 1; okf = 1; }
        __syncthreads();
        const unsigned int* p = (const unsigned int*)m;
        for (int idx = tid; idx < 4096; idx += 256) {
            unsigned int v = p[idx];
            if (v != 0u && v != 1u) oki = 0;
            float f = __uint_as_float(v);
            if (f != 0.0f && f != 1.0f) okf = 0;
        }
        __syncthreads();
        if (tid == 0) d_mask_mode = oki ? 0 : (okf ? 1 : 2);
    }
}

// ---------------------------------------------------------------------------
// Mask -> AND half-word table (keep=0xFFFF, masked=0x0000).
// ---------------------------------------------------------------------------
__global__ void k_maskpack(const void* __restrict__ m) {
    int n = blockIdx.x;
    int j = threadIdx.x;
    int mode = d_mask_mode;
    bool v;
    if (mode == 0)      v = ((const int*)m)[n*NN + j] != 0;
    else if (mode == 1) v = ((const float*)m)[n*NN + j] != 0.0f;
    else                v = ((const unsigned char*)m)[n*NN + j] != 0;
    ((unsigned short*)d_ms)[n*NN + j] = v ? 0 : 0xFFFFu;
}

// ---------------------------------------------------------------------------
// Permute mask words into per-(tile,cw,s,lane) uint2 layout so the attention
// inner loop reads them as coalesced 256B warp loads.
// ---------------------------------------------------------------------------
__global__ void k_maskperm() {
    int idx = blockIdx.x*256 + threadIdx.x;     // 65536 entries
    int lane = idx & 31;
    int s    = (idx >> 5) & 3;
    int cw   = (idx >> 7) & 15;
    int tile = idx >> 11;
    int g = lane >> 2, tq = lane & 3;
    int row0 = tile*16 + g;
    int w = cw*16 + s*4 + tq;
    uint2 v;
    v.x = d_ms[row0*256 + w];
    v.y = d_ms[(row0 + 8)*256 + w];
    d_msp[idx] = v;
}

// ---------------------------------------------------------------------------
// Kernel 1: QKV as bf16 MMA GEMM (R12-proven). V epilogue now stores f16.
// ---------------------------------------------------------------------------
__global__ __launch_bounds__(256) void k_qkv2(const float* __restrict__ x) {
    __shared__ unsigned xs[128*36];   // [n_local][ci-pair], padded stride 36
    int bt = blockIdx.x, nq = blockIdx.y;
    int b = bt / NT, t = bt % NT;
    int tid = threadIdx.x;

    const float* xg = x + (long long)b*64*6144 + t*512 + nq*128;
    #pragma unroll 4
    for (int it = 0; it < 16; it++) {
        int idx = it*256 + tid;
        int cp = idx >> 7, nl = idx & 127;
        float f0 = __ldg(xg + (2*cp)*6144 + nl);
        float f1 = __ldg(xg + (2*cp+1)*6144 + nl);
        xs[nl*36 + cp] = bf2(f0, f1);
    }
    __syncthreads();

    int lane = tid & 31, w = tid >> 5;
    int g = lane >> 2, tq = lane & 3;
    int mset0 = w & 3;
    int nrb = (w >> 2) * 8;

    unsigned A[3][4][4];
    float bia[3][2];
    #pragma unroll
    for (int mi = 0; mi < 3; mi++) {
        int mt = mset0 + mi*4;
        int R0 = mt*16 + g, R1 = R0 + 8;
        bia[mi][0] = d_bc[R0]; bia[mi][1] = d_bc[R1];
        const unsigned* w0 = (const unsigned*)(d_wcb + R0*64);
        const unsigned* w1 = (const unsigned*)(d_wcb + R1*64);
        #pragma unroll
        for (int ks = 0; ks < 4; ks++) {
            A[mi][ks][0] = __ldg(w0 + ks*8 + tq);
            A[mi][ks][1] = __ldg(w1 + ks*8 + tq);
            A[mi][ks][2] = __ldg(w0 + ks*8 + 4 + tq);
            A[mi][ks][3] = __ldg(w1 + ks*8 + 4 + tq);
        }
    }

    for (int nt0 = 0; nt0 < 8; nt0++) {
        int ntile = nrb + nt0;
        const unsigned* xr = xs + (ntile*8 + g)*36;
        unsigned B[4][2];
        #pragma unroll
        for (int ks = 0; ks < 4; ks++) { B[ks][0] = xr[ks*8 + tq]; B[ks][1] = xr[ks*8 + 4 + tq]; }

        #pragma unroll
        for (int mi = 0; mi < 3; mi++) {
            float c0 = bia[mi][0], c1 = bia[mi][0], c2 = bia[mi][1], c3 = bia[mi][1];
            #pragma unroll
            for (int ks = 0; ks < 4; ks++)
                mma16816(c0,c1,c2,c3, A[mi][ks][0],A[mi][ks][1],A[mi][ks][2],A[mi][ks][3],
                         B[ks][0], B[ks][1], c0,c1,c2,c3);

            int mt = mset0 + mi*4;
            int R0 = mt*16 + g;
            int g6 = mt >> 1;
            int o0 = R0 & 31, h0 = o0 >> 3, d0 = o0 & 7;
            int n = nq*128 + ntile*8 + 2*tq;
            if (g6 == 2 || g6 == 5) {
                int vi = (g6 == 5);
                unsigned short* vt0 = d_vt + ((((vi*NBT + bt)*4 + h0    )*8 + d0)*NN);
                unsigned short* vt1 = d_vt + ((((vi*NBT + bt)*4 + h0 + 1)*8 + d0)*NN);
                *(unsigned*)(vt0 + n) = h2p(c0, c1);   // f16 pair
                *(unsigned*)(vt1 + n) = h2p(c2, c3);
            } else {
                int qi = (g6 < 2) ? g6 : g6 - 1;
                __nv_bfloat16* q0 = d_qt + (((qi*NBT + bt)*4 + h0    )*NN)*8;
                __nv_bfloat16* q1 = d_qt + (((qi*NBT + bt)*4 + h0 + 1)*NN)*8;
                q0[n*8 + d0]     = __float2bfloat16(c0);
                q0[(n+1)*8 + d0] = __float2bfloat16(c1);
                q1[n*8 + d0]     = __float2bfloat16(c2);
                q1[(n+1)*8 + d0] = __float2bfloat16(c3);
            }
        }
    }
}

// ---------------------------------------------------------------------------
// Kernel 2: flash attention. QK bf16 k8; exp via ex2.approx.f16x2 (1 MUFU /
// 2 keys); P,V f16; PV + denominator via f16 m16n8k16. Mask = coalesced
// uint2 AND-words from the permuted table.
// ---------------------------------------------------------------------------
#define VSTRIDE 1040   // 1040/4 = 260 ≡ 4 (mod 32) -> banks 4g+tq distinct

template<bool MASKED>
__device__ __forceinline__ void attn_loop6(
    unsigned ksb, unsigned vsb,
    const unsigned* __restrict__ qgu,
    float* __restrict__ outp)
{
    int tid = threadIdx.x, lane = tid & 31, wid = tid >> 5;
    int g = lane >> 2, tq = lane & 3;
    unsigned kbase = ksb + g*16 + tq*4;
    unsigned vbase = vsb + g*VSTRIDE + tq*4;

    for (int tile = wid; tile < 32; tile += 4) {
        int r0 = tile*16 + g, r1 = r0 + 8;
        unsigned qa0 = __ldg(qgu + r0*4 + tq);
        unsigned qa1 = __ldg(qgu + r1*4 + tq);
        const uint2* mp = d_msp + tile*2048 + lane;

        float o0=0.f,o1=0.f,o2=0.f,o3=0.f;
        float L0=0.f,L1=0.f,L2=0.f,L3=0.f;

        #pragma unroll
        for (int cw = 0; cw < 16; cw++) {
            uint2 mm[4];
            if (MASKED) {
                #pragma unroll
                for (int s = 0; s < 4; s++) mm[s] = __ldg(mp + (cw*4 + s)*32);
            }
            unsigned pa[8];
            #pragma unroll
            for (int s = 0; s < 4; s++) {
                unsigned kb = lds32o<0>(kbase + (cw*4 + s)*128);
                float s0,s1,s2,s3;
                mma_bf16(s0,s1,s2,s3, qa0,qa1, kb, 0.f,0.f,0.f,0.f);
                unsigned x0 = ex2h2(h2p(s0, s1));
                unsigned x1 = ex2h2(h2p(s2, s3));
                if (MASKED) { x0 &= mm[s].x; x1 &= mm[s].y; }
                pa[2*s] = x0; pa[2*s+1] = x1;
            }
            #pragma unroll
            for (int hf = 0; hf < 2; hf++) {
                unsigned a0 = pa[hf*4+0], a1 = pa[hf*4+1], a2 = pa[hf*4+2], a3 = pa[hf*4+3];
                mma16816h(L0,L1,L2,L3, a0,a1,a2,a3, ONESH,ONESH, L0,L1,L2,L3);
                unsigned vb0 = lds32o<0> (vbase + cw*64 + hf*32);
                unsigned vb1 = lds32o<16>(vbase + cw*64 + hf*32);
                mma16816h(o0,o1,o2,o3, a0,a1,a2,a3, vb0,vb1, o0,o1,o2,o3);
            }
        }
        float inv0 = rcpf(L0), inv1 = rcpf(L2);
        *(float2*)&outp[r0*8 + 2*tq] = make_float2(o0*inv0, o1*inv0);
        *(float2*)&outp[r1*8 + 2*tq] = make_float2(o2*inv1, o3*inv1);
    }
}

__global__ __launch_bounds__(128) void k_attn6() {
    __shared__ __align__(16) unsigned char ksm[NN*16];       // K [n][8] bf16
    __shared__ __align__(16) unsigned char vsm[8*VSTRIDE];   // V [d][n] f16, padded
    int bt = blockIdx.x, h = blockIdx.y, blk = blockIdx.z;
    int tid = threadIdx.x;

    int qi = blk ? 2 : 0;
    int ki = blk ? 3 : 1;
    int vi = blk ? 1 : 0;

    const __nv_bfloat16* qg = d_qt + ((((long long)qi*NBT + bt)*4 + h)*NN)*8;
    const __nv_bfloat16* kg = d_qt + ((((long long)ki*NBT + bt)*4 + h)*NN)*8;
    const unsigned short* vg = d_vt + ((((long long)vi*NBT + bt)*4 + h)*8)*NN;

    {
        const uint4* kg4 = (const uint4*)kg;
        const uint4* vg4 = (const uint4*)vg;
        uint4* ks4 = (uint4*)ksm;
        for (int i = tid; i < 512; i += 128) {
            ks4[i] = kg4[i];
            uint4 v = vg4[i];
            int r = i >> 6, c = i & 63;
            *(uint4*)(vsm + r*VSTRIDE + c*16) = v;
        }
    }
    __syncthreads();

    unsigned ksb = (unsigned)__cvta_generic_to_shared(ksm);
    unsigned vsb = (unsigned)__cvta_generic_to_shared(vsm);
    int b = bt / NT, t = bt % NT;
    float* outp = d_attn + (blk*NB + b)*(4*NT*NN*8) + (h*NT + t)*(NN*8);

    if (blk == 0) attn_loop6<true >(ksb, vsb, (const unsigned*)qg, outp);
    else          attn_loop6<false>(ksb, vsb, (const unsigned*)qg, outp);
}

// ---------------------------------------------------------------------------
// Kernel 3: coalesced torch-faithful gather + residual + ReLU (proven).
// ---------------------------------------------------------------------------
__global__ __launch_bounds__(256) void k_final(const float* __restrict__ x,
                                               float* __restrict__ out) {
    __shared__ float sm[128*33];
    int bt = blockIdx.x, sel = blockIdx.y, ntile = blockIdx.z;
    int tid = threadIdx.x;
    int b = bt / NT, t = bt % NT;
    int n0 = ntile * 128;
    int blk = 1 - sel;
    int cbase = sel * 32;

    const float* ab = d_attn + (blk*NB + b)*(4*NT*NN*8);
    for (int idx = tid; idx < 128*32; idx += 256) {
        int r = idx >> 5, cc = idx & 31;
        sm[r*33 + cc] = ab[(n0 + r)*384 + t*32 + cc];
    }
    __syncthreads();

    int nl = tid & 127, chalf = tid >> 7;
    #pragma unroll
    for (int k = 0; k < 16; k++) {
        int cl = k*2 + chalf;
        int c = cbase + cl;
        long long xi = ((long long)(b*64 + c)*NT + t)*NN + n0 + nl;
        out[xi] = fmaxf(sm[nl*33 + cl] + x[xi], 0.f);
    }
}

// ---------------------------------------------------------------------------
extern "C" void kernel_launch(void* const* d_in, const int* in_sizes, int n_in,
                              void* d_out, int out_size) {
    const float* x    = (const float*)d_in[0];
    const void*  mask = d_in[1];
    const float* wp   = (const float*)d_in[2];
    const float* bp   = (const float*)d_in[3];
    WPtrs P;
    for (int g = 0; g < 6; g++) {
        P.w[g] = (const float*)d_in[4 + 2*g];
        P.b[g] = (const float*)d_in[5 + 2*g];
    }

    k_setup   <<<25, 256>>>(wp, bp, P, mask);
    k_maskpack<<<NN, NN>>>(mask);
    k_maskperm<<<256, 256>>>();
    k_qkv2    <<<dim3(NBT, 4), 256>>>(x);
    k_attn6   <<<dim3(NBT, 4, 2), 128>>>();
    k_final   <<<dim3(NBT, 2, 4), 256>>>(x, (float*)d_out);
}